// round 8
// baseline (speedup 1.0000x reference)
#include <cuda_runtime.h>
#include <cuda_fp16.h>
#include <cstdint>
#include <math.h>

typedef __half f16;

// ===========================================================================
// TriParser via mma.sync (HMMA fp16, f32 acc), split-fp16 2-product emu.
//   proj: elu(h@W+b) -> f16 hi|lo rows [1024, 512]   (7 branches)
//   Up:   U[a,c,d] -> rows r=d*256+c, cols a hi|lo   [65536, 512]
//   stage1: t1[bi][d][c] = u @ Up^T
//   stage2: t2[bi][j][d] = v[b] @ t1[bi]^T
//   stage3: s[bi][j][k]  = t2[bi] @ w[b]^T  (f32 out)
// D = Ah@Bh + Ah@Bl. HMMA scheduling: all Bh products, then all Bl products,
// so dependent accumulator writes are 16 MMAs apart (covers HMMA latency).
// ===========================================================================

__device__ float g_h[1024 * 512];                      // 2 MB
__device__ f16   g_projb[7 * 1024 * 512];              // 7 MB
__device__ f16   g_Up[3ull * 65536 * 512];             // 192 MB
__device__ f16   g_t1[3ull * 1024 * 256 * 512];        // 804 MB (slice per tri)
__device__ f16   g_t2[1024ull * 128 * 512];            // 134 MB

__device__ __forceinline__ uint32_t smem_u32(const void* p) {
    uint32_t a;
    asm("{ .reg .u64 t; cvta.to.shared.u64 t, %1; cvt.u32.u64 %0, t; }"
        : "=r"(a) : "l"(p));
    return a;
}

#define SW128(o) ((o) ^ (((o) >> 3) & 0x70))

__device__ __forceinline__ void ldm_x4(uint32_t* r, uint32_t addr) {
    asm volatile("ldmatrix.sync.aligned.m8n8.x4.shared.b16 {%0,%1,%2,%3}, [%4];"
                 : "=r"(r[0]), "=r"(r[1]), "=r"(r[2]), "=r"(r[3]) : "r"(addr));
}

__device__ __forceinline__ void mma16816(float* c, const uint32_t* a, const uint32_t* b) {
    asm volatile(
        "mma.sync.aligned.m16n8k16.row.col.f32.f16.f16.f32 "
        "{%0,%1,%2,%3}, {%4,%5,%6,%7}, {%8,%9}, {%0,%1,%2,%3};"
        : "+f"(c[0]), "+f"(c[1]), "+f"(c[2]), "+f"(c[3])
        : "r"(a[0]), "r"(a[1]), "r"(a[2]), "r"(a[3]), "r"(b[0]), "r"(b[1]));
}

__device__ __forceinline__ void cpa16(uint32_t dst, const void* src) {
    asm volatile("cp.async.cg.shared.global [%0], [%1], 16;" :: "r"(dst), "l"(src) : "memory");
}
#define CP_COMMIT() asm volatile("cp.async.commit_group;" ::: "memory")
#define CP_WAIT1()  asm volatile("cp.async.wait_group 1;" ::: "memory")
#define CP_WAIT0()  asm volatile("cp.async.wait_group 0;" ::: "memory")

// Packed tile loader: source rows [row, 512] f16 (hi 0:256 | lo 256:512).
// Chunk c covers K cols [c*32, c*32+32). Tile = 128 rows x 128B (hi|lo), SW128.
__device__ __forceinline__ void load_packed(const f16* __restrict__ g, int c,
                                            uint32_t dst, int tid) {
#pragma unroll
    for (int i = 0; i < 4; i++) {
        int idx = tid + i * 256;
        int row = idx >> 3, seg = idx & 7;
        int col = (seg < 4) ? c * 32 + seg * 8 : 256 + c * 32 + (seg - 4) * 8;
        cpa16(dst + SW128(row * 128 + seg * 16), g + (size_t)row * 512 + col);
    }
}

// One K-chunk(32): 2-product MMA, warp tile 32x64 (wm 0-3, wn 0-1).
// Scheduling: all 16 Bh-product MMAs, then all 16 Bl-product MMAs -> 16-instr
// spacing between dependent writes to the same accumulator.
__device__ __forceinline__ void mma_chunk(uint32_t aBase, uint32_t bBase,
                                          float (&acc)[2][8][4],
                                          int aLB, int bLB, int wm, int wn) {
#pragma unroll
    for (int kk = 0; kk < 2; kk++) {
        uint32_t ah[2][4], bh[4][4], bl[4][4];
#pragma unroll
        for (int mi = 0; mi < 2; mi++) {
            int off = aLB + (wm * 32 + mi * 16) * 128 + kk * 32;
            ldm_x4(ah[mi], aBase + SW128(off));
        }
#pragma unroll
        for (int nj = 0; nj < 4; nj++) {
            int off = bLB + (wn * 64 + nj * 16) * 128 + kk * 32;
            ldm_x4(bh[nj], bBase + SW128(off));
            ldm_x4(bl[nj], bBase + SW128(off + 64));
        }
        // pass 1: Bh products (16 independent MMAs)
#pragma unroll
        for (int mi = 0; mi < 2; mi++)
#pragma unroll
            for (int nj = 0; nj < 4; nj++) {
                mma16816(acc[mi][nj * 2],     ah[mi], &bh[nj][0]);
                mma16816(acc[mi][nj * 2 + 1], ah[mi], &bh[nj][2]);
            }
        // pass 2: Bl products (re-touch each acc 16 MMAs later)
#pragma unroll
        for (int mi = 0; mi < 2; mi++)
#pragma unroll
            for (int nj = 0; nj < 4; nj++) {
                mma16816(acc[mi][nj * 2],     ah[mi], &bl[nj][0]);
                mma16816(acc[mi][nj * 2 + 1], ah[mi], &bl[nj][2]);
            }
    }
}

#define ZERO_ACC(acc) \
    { _Pragma("unroll") for (int i = 0; i < 2; i++) \
      _Pragma("unroll") for (int j = 0; j < 8; j++) \
      _Pragma("unroll") for (int k = 0; k < 4; k++) acc[i][j][k] = 0.0f; }

// ===========================================================================
// Generic MMA stage, 256 threads, 2 CTAs/SM, 2-deep pipeline.
// ===========================================================================
template <int EPI, int S1MAP>
__global__ __launch_bounds__(256, 2)
void mma_stage(const f16* __restrict__ A, const f16* __restrict__ B,
               void* __restrict__ Cv,
               unsigned long long aBatch, int aShift,
               unsigned long long bBatch, int bShift,
               unsigned long long cBatch, unsigned long long cRowStride)
{
    extern __shared__ char dsm[];
    const uint32_t sraw = smem_u32(dsm);
    const uint32_t sb = (sraw + 1023u) & ~1023u;

    const int tid = threadIdx.x;
    const int lane = tid & 31;
    const int warp = tid >> 5;
    const int wm = warp >> 1, wn = warp & 1;
    const int aLB = ((lane & 15) * 128) + ((lane >> 4) * 16);
    const int bLB = (((lane & 7) + ((lane >> 4) << 3)) * 128) + (((lane >> 3) & 1) * 16);
    const size_t z = blockIdx.z;

    const f16* Ab = A + (z >> aShift) * (size_t)aBatch + (size_t)blockIdx.x * 65536;
    const f16* Bb = B + (z >> bShift) * (size_t)bBatch + (size_t)blockIdx.y * 65536;

    float acc[2][8][4];
    ZERO_ACC(acc);

    auto issue = [&](int c) {
        uint32_t buf = sb + (c & 1) * 32768;
        load_packed(Ab, c, buf, tid);
        load_packed(Bb, c, buf + 16384, tid);
        CP_COMMIT();
    };
    issue(0); issue(1);

#pragma unroll
    for (int c = 0; c < 8; c++) {
        if (c < 7) CP_WAIT1(); else CP_WAIT0();
        __syncthreads();
        uint32_t buf = sb + (c & 1) * 32768;
        mma_chunk(buf, buf + 16384, acc, aLB, bLB, wm, wn);
        if (c < 6) { __syncthreads(); issue(c + 2); }
    }

    const int gRow = lane >> 2;
    const int cPair = (lane & 3) * 2;

    if (EPI == 0) {
        f16* Cb = (f16*)Cv + z * cBatch;
        const size_t colBase = S1MAP
            ? ((size_t)(blockIdx.y >> 1) * 512 + (size_t)(blockIdx.y & 1) * 128)
            : (size_t)blockIdx.y * 128;
#pragma unroll
        for (int mi = 0; mi < 2; mi++) {
            int rbase = blockIdx.x * 128 + wm * 32 + mi * 16 + gRow;
#pragma unroll
            for (int f = 0; f < 8; f++) {
                int nloc = wn * 64 + f * 8 + cPair;
#pragma unroll
                for (int hh = 0; hh < 2; hh++) {
                    float v0 = acc[mi][f][hh * 2 + 0];
                    float v1 = acc[mi][f][hh * 2 + 1];
                    size_t row = (size_t)(rbase + hh * 8);
                    f16 h0 = __float2half(v0);
                    f16 l0 = __float2half(v0 - __half2float(h0));
                    f16 h1 = __float2half(v1);
                    f16 l1 = __float2half(v1 - __half2float(h1));
                    __half2 ph; ph.x = h0; ph.y = h1;
                    __half2 pl; pl.x = l0; pl.y = l1;
                    *(__half2*)(Cb + row * cRowStride + colBase + nloc) = ph;
                    *(__half2*)(Cb + row * cRowStride + colBase + 256 + nloc) = pl;
                }
            }
        }
    } else {
        float* Cb = (float*)Cv + z * cBatch;
#pragma unroll
        for (int mi = 0; mi < 2; mi++) {
            int rbase = blockIdx.x * 128 + wm * 32 + mi * 16 + gRow;
#pragma unroll
            for (int f = 0; f < 8; f++) {
                int col = blockIdx.y * 128 + wn * 64 + f * 8 + cPair;
#pragma unroll
                for (int hh = 0; hh < 2; hh++) {
                    size_t row = (size_t)(rbase + hh * 8);
                    *(float2*)(Cb + row * 128 + col) =
                        make_float2(acc[mi][f][hh * 2 + 0], acc[mi][f][hh * 2 + 1]);
                }
            }
        }
    }
}

// ===========================================================================
// Projection GEMM (SIMT fp32): elu(h @ W + b) -> f16 hi|lo rows [1024,512]
// ===========================================================================
struct ProjArgs {
    const float* W[7];
    const float* bias[7];
};

__global__ __launch_bounds__(256, 2)
void proj_gemm(ProjArgs pa, const float* __restrict__ h, f16* __restrict__ outp)
{
    __shared__ float As[16][128];
    __shared__ float Bs[16][128];

    const int br = blockIdx.z;
    const float* A = h;
    const float* B = pa.W[br];
    const float* bias = pa.bias[br];

    const int tid = threadIdx.x;
    const int bm = blockIdx.y * 128;
    const int bn = blockIdx.x * 128;
    const int tx = tid & 15;
    const int ty = tid >> 4;

    float acc[8][8];
#pragma unroll
    for (int i = 0; i < 8; i++)
#pragma unroll
        for (int j = 0; j < 8; j++) acc[i][j] = 0.0f;

    for (int k0 = 0; k0 < 512; k0 += 16) {
#pragma unroll
        for (int i = 0; i < 2; i++) {
            int v = tid + i * 256;
            int r = v >> 2;
            int c4 = (v & 3) << 2;
            float4 a = *(const float4*)(A + (size_t)(bm + r) * 512 + k0 + c4);
            As[c4 + 0][r] = a.x; As[c4 + 1][r] = a.y;
            As[c4 + 2][r] = a.z; As[c4 + 3][r] = a.w;
        }
#pragma unroll
        for (int i = 0; i < 2; i++) {
            int v = tid + i * 256;
            int r = v >> 5;
            int c4 = (v & 31) << 2;
            float4 b = *(const float4*)(B + (size_t)(k0 + r) * 256 + bn + c4);
            *(float4*)&Bs[r][c4] = b;
        }
        __syncthreads();
#pragma unroll
        for (int kk = 0; kk < 16; kk++) {
            float ar[8], brg[8];
            *(float4*)&ar[0] = *(const float4*)&As[kk][ty * 8];
            *(float4*)&ar[4] = *(const float4*)&As[kk][ty * 8 + 4];
            *(float4*)&brg[0] = *(const float4*)&Bs[kk][tx * 8];
            *(float4*)&brg[4] = *(const float4*)&Bs[kk][tx * 8 + 4];
#pragma unroll
            for (int i = 0; i < 8; i++)
#pragma unroll
                for (int j = 0; j < 8; j++)
                    acc[i][j] = fmaf(ar[i], brg[j], acc[i][j]);
        }
        __syncthreads();
    }

    f16* Co = outp + (size_t)br * (1024 * 512);
#pragma unroll
    for (int i = 0; i < 8; i++) {
        int r = bm + ty * 8 + i;
#pragma unroll
        for (int j = 0; j < 8; j++) {
            int col = bn + tx * 8 + j;
            float v = acc[i][j] + bias[col];
            v = v > 0.f ? v : expm1f(v);
            f16 hb = __float2half(v);
            f16 lb = __float2half(v - __half2float(hb));
            Co[(size_t)r * 512 + col] = hb;
            Co[(size_t)r * 512 + 256 + col] = lb;
        }
    }
}

// ===========================================================================
// U permute+split: U[a,c,d] f32 -> Up[(d*256+c)][a] hi, [(d*256+c)][256+a] lo
// ===========================================================================
__global__ void uconv(const float* __restrict__ U, f16* __restrict__ Up)
{
    __shared__ float t[32][33];
    const int c = blockIdx.z;
    const int d0 = blockIdx.x * 32;
    const int a0 = blockIdx.y * 32;
    const int tx = threadIdx.x;
    const int ty = threadIdx.y;

#pragma unroll
    for (int i = 0; i < 32; i += 8)
        t[ty + i][tx] = U[(size_t)(a0 + ty + i) * 65536 + c * 256 + d0 + tx];
    __syncthreads();
#pragma unroll
    for (int i = 0; i < 32; i += 8) {
        int dl = ty + i;
        float v = t[tx][dl];
        f16 hb = __float2half(v);
        f16 lb = __float2half(v - __half2float(hb));
        size_t rowbase = ((size_t)(d0 + dl) * 256 + c) * 512;
        Up[rowbase + a0 + tx] = hb;
        Up[rowbase + 256 + a0 + tx] = lb;
    }
}

__global__ void build_h(const float* __restrict__ x, const float* __restrict__ sent,
                        float* __restrict__ h)
{
    int idx = blockIdx.x * blockDim.x + threadIdx.x;
    int rowi = idx >> 9;
    int e = idx & 511;
    int t = rowi & 127;
    int b = rowi >> 7;
    h[idx] = (t == 0) ? sent[e] : x[((size_t)(b * 127 + t - 1)) * 512 + e];
}

__global__ void write_mask(const int* __restrict__ mask, float* __restrict__ outm)
{
    int i = blockIdx.x * blockDim.x + threadIdx.x;
    if (i < 1024) {
        int b = i >> 7, t = i & 127;
        outm[i] = (t == 0) ? 1.0f : (float)mask[b * 127 + t - 1];
    }
}

// ===========================================================================
extern "C" void kernel_launch(void* const* d_in, const int* in_sizes, int n_in,
                              void* d_out, int out_size)
{
    (void)in_sizes; (void)n_in; (void)out_size;

    const float* x    = (const float*)d_in[0];
    const int*   mask = (const int*)d_in[2];
    const float* U[3] = { (const float*)d_in[17], (const float*)d_in[18], (const float*)d_in[19] };
    const float* sent = (const float*)d_in[20];
    float* out = (float*)d_out;

    float* h;
    f16 *projb, *Up, *t1, *t2;
    cudaGetSymbolAddress((void**)&h,     g_h);
    cudaGetSymbolAddress((void**)&projb, g_projb);
    cudaGetSymbolAddress((void**)&Up,    g_Up);
    cudaGetSymbolAddress((void**)&t1,    g_t1);
    cudaGetSymbolAddress((void**)&t2,    g_t2);

    const int SMEM = 2 * 32768 + 1024;   // 66560 -> 2 CTAs/SM
    cudaFuncSetAttribute(mma_stage<0, 1>, cudaFuncAttributeMaxDynamicSharedMemorySize, SMEM);
    cudaFuncSetAttribute(mma_stage<0, 0>, cudaFuncAttributeMaxDynamicSharedMemorySize, SMEM);
    cudaFuncSetAttribute(mma_stage<1, 0>, cudaFuncAttributeMaxDynamicSharedMemorySize, SMEM);

    ProjArgs pa;
    for (int i = 0; i < 7; i++) {
        pa.W[i]    = (const float*)d_in[3 + 2 * i];
        pa.bias[i] = (const float*)d_in[4 + 2 * i];
    }

    const size_t PB = 1024 * 512;
    const size_t UPS = (size_t)65536 * 512;
    const size_t T1S = (size_t)1024 * 256 * 512;
    const int ui[3] = {0, 2, 4};
    const int vi[3] = {1, 3, 6};
    const int wi[3] = {1, 2, 5};

    auto stage1 = [&](int t) {
        mma_stage<0, 1><<<dim3(8, 512, 1), 256, SMEM>>>(
            projb + ui[t] * PB, Up + t * UPS, t1 + t * T1S,
            0ULL, 0, 0ULL, 0, 0ULL, 131072ULL);
    };
    auto stage2 = [&](int t) {
        mma_stage<0, 0><<<dim3(1, 2, 1024), 256, SMEM>>>(
            projb + vi[t] * PB, t1 + t * T1S, t2,
            65536ULL, 7, 131072ULL, 0, 65536ULL, 512ULL);
    };
    auto stage3 = [&](int t) {
        mma_stage<1, 0><<<dim3(1, 1, 1024), 256, SMEM>>>(
            t2, projb + wi[t] * PB, out + (size_t)t * 16777216,
            65536ULL, 0, 65536ULL, 7, 16384ULL, 128ULL);
    };

    // launch order: profiled slot (index 3) = stage1(0)
    build_h<<<2048, 256>>>(x, sent, h);                              // 0
    proj_gemm<<<dim3(2, 8, 7), 256>>>(pa, h, projb);                 // 1
    uconv<<<dim3(8, 8, 256), dim3(32, 8)>>>(U[0], Up + 0 * UPS);     // 2
    stage1(0);                                                       // 3 <- ncu
    uconv<<<dim3(8, 8, 256), dim3(32, 8)>>>(U[1], Up + 1 * UPS);
    uconv<<<dim3(8, 8, 256), dim3(32, 8)>>>(U[2], Up + 2 * UPS);
    stage1(1);
    stage1(2);
    stage2(0); stage3(0);
    stage2(1); stage3(1);
    stage2(2); stage3(2);
    write_mask<<<4, 256>>>(mask, out + (size_t)3 * 16777216);
}

// round 9
// speedup vs baseline: 1.1672x; 1.1672x over previous
#include <cuda_runtime.h>
#include <cuda_fp16.h>
#include <cstdint>
#include <math.h>

typedef __half f16;

// ===========================================================================
// TriParser via mma.sync (HMMA fp16, f32 acc), split-fp16 2-product emu.
//   proj: elu(h@W+b) -> f16 hi|lo rows [1024, 512]   (7 branches)
//   Up:   U[a,c,d] -> rows r=d*256+c, cols a hi|lo   [65536, 512]
//   stage1: t1[bi][r] = u(hi) @ Up^T          (B split; t1 stored HI-only)
//   stage2: t2[bi][j][d] = v(hi+lo) @ t1^T    (A split; t2 stored HI-only)
//   stage3: s[bi][j][k]  = t2(hi) @ w^T       (B split; f32 out)
// Every product keeps exactly one ~22-bit (hi+lo) operand; dropped term 2^-12.
// Stage1: M-tile 256, A resident in smem, N-loop (8 tiles) -> L2 traffic /3.
// ===========================================================================

__device__ float g_h[1024 * 512];                      // 2 MB
__device__ f16   g_projb[7 * 1024 * 512];              // 7 MB
__device__ f16   g_Up[3ull * 65536 * 512];             // 192 MB
__device__ f16   g_t1[3ull * 1024 * 65536];            // 402 MB (hi only)
__device__ f16   g_t2[1024ull * 128 * 256];            // 67 MB (hi only)

__device__ __forceinline__ uint32_t smem_u32(const void* p) {
    uint32_t a;
    asm("{ .reg .u64 t; cvta.to.shared.u64 t, %1; cvt.u32.u64 %0, t; }"
        : "=r"(a) : "l"(p));
    return a;
}

#define SW128(o) ((o) ^ (((o) >> 3) & 0x70))

__device__ __forceinline__ void ldm_x4(uint32_t* r, uint32_t addr) {
    asm volatile("ldmatrix.sync.aligned.m8n8.x4.shared.b16 {%0,%1,%2,%3}, [%4];"
                 : "=r"(r[0]), "=r"(r[1]), "=r"(r[2]), "=r"(r[3]) : "r"(addr));
}

__device__ __forceinline__ void mma16816(float* c, const uint32_t* a, const uint32_t* b) {
    asm volatile(
        "mma.sync.aligned.m16n8k16.row.col.f32.f16.f16.f32 "
        "{%0,%1,%2,%3}, {%4,%5,%6,%7}, {%8,%9}, {%0,%1,%2,%3};"
        : "+f"(c[0]), "+f"(c[1]), "+f"(c[2]), "+f"(c[3])
        : "r"(a[0]), "r"(a[1]), "r"(a[2]), "r"(a[3]), "r"(b[0]), "r"(b[1]));
}

__device__ __forceinline__ void cpa16(uint32_t dst, const void* src) {
    asm volatile("cp.async.cg.shared.global [%0], [%1], 16;" :: "r"(dst), "l"(src) : "memory");
}
#define CP_COMMIT() asm volatile("cp.async.commit_group;" ::: "memory")
#define CP_WAIT1()  asm volatile("cp.async.wait_group 1;" ::: "memory")
#define CP_WAIT0()  asm volatile("cp.async.wait_group 0;" ::: "memory")

// SPLIT K32 tile (16KB): 128 rows x 128B = hi(64B)|lo(64B). src rows [row,512].
__device__ __forceinline__ void load_split(const f16* __restrict__ g, int c32,
                                           uint32_t dst, int tid) {
#pragma unroll
    for (int i = 0; i < 4; i++) {
        int idx = tid + i * 256;
        int row = idx >> 3, seg = idx & 7;
        int col = (seg < 4) ? c32 * 32 + seg * 8 : 256 + c32 * 32 + (seg - 4) * 8;
        cpa16(dst + SW128(row * 128 + seg * 16), g + (size_t)row * 512 + col);
    }
}

// PLAIN K64 tile (16KB): 128 rows x 128B of hi-only data, rowstride rs (f16).
__device__ __forceinline__ void load_plain(const f16* __restrict__ g, int rs, int c64,
                                           uint32_t dst, int tid) {
#pragma unroll
    for (int i = 0; i < 4; i++) {
        int idx = tid + i * 256;
        int row = idx >> 3, seg = idx & 7;
        cpa16(dst + SW128(row * 128 + seg * 16), g + (size_t)row * rs + c64 * 64 + seg * 8);
    }
}

// PLAIN K64 tile, 256 rows (32KB), for stage1 resident A.
__device__ __forceinline__ void load_plain256(const f16* __restrict__ g, int rs, int c64,
                                              uint32_t dst, int tid) {
#pragma unroll
    for (int i = 0; i < 8; i++) {
        int idx = tid + i * 256;
        int row = idx >> 3, seg = idx & 7;
        cpa16(dst + SW128(row * 128 + seg * 16), g + (size_t)row * rs + c64 * 64 + seg * 8);
    }
}

// ---------------------------------------------------------------------------
// One K64 unit. X = split operand (2 SPLIT tiles at xb, xb+16K), Y = plain
// (1 PLAIN K64 tile at yb). SPLITA: X is the A operand, else X is B.
// Warp tile (MI*16) x 64. wm in 0..3, wn in 0..1.
// ---------------------------------------------------------------------------
template <int MI, bool SPLITA>
__device__ __forceinline__ void mma_unit(uint32_t xb, uint32_t yb,
                                         float (&acc)[MI][8][4],
                                         int aLB, int bLB, int wm, int wn) {
#pragma unroll
    for (int kk = 0; kk < 4; kk++) {
        const uint32_t xt = xb + (kk >> 1) * 16384;
        const int off32 = (kk & 1) * 32;
        if (SPLITA) {
            uint32_t ah[MI][4], al[MI][4], bq[4][4];
#pragma unroll
            for (int mi = 0; mi < MI; mi++) {
                int off = aLB + (wm * (MI * 16) + mi * 16) * 128 + off32;
                ldm_x4(ah[mi], xt + SW128(off));
                ldm_x4(al[mi], xt + SW128(off + 64));
            }
#pragma unroll
            for (int nj = 0; nj < 4; nj++) {
                int off = bLB + (wn * 64 + nj * 16) * 128 + kk * 32;
                ldm_x4(bq[nj], yb + SW128(off));
            }
#pragma unroll
            for (int mi = 0; mi < MI; mi++)
#pragma unroll
                for (int nj = 0; nj < 4; nj++) {
                    mma16816(acc[mi][nj * 2],     ah[mi], &bq[nj][0]);
                    mma16816(acc[mi][nj * 2 + 1], ah[mi], &bq[nj][2]);
                }
#pragma unroll
            for (int mi = 0; mi < MI; mi++)
#pragma unroll
                for (int nj = 0; nj < 4; nj++) {
                    mma16816(acc[mi][nj * 2],     al[mi], &bq[nj][0]);
                    mma16816(acc[mi][nj * 2 + 1], al[mi], &bq[nj][2]);
                }
        } else {
            uint32_t aq[MI][4], bh[4][4], bl[4][4];
#pragma unroll
            for (int mi = 0; mi < MI; mi++) {
                int off = aLB + (wm * (MI * 16) + mi * 16) * 128 + kk * 32;
                ldm_x4(aq[mi], yb + SW128(off));
            }
#pragma unroll
            for (int nj = 0; nj < 4; nj++) {
                int off = bLB + (wn * 64 + nj * 16) * 128 + off32;
                ldm_x4(bh[nj], xt + SW128(off));
                ldm_x4(bl[nj], xt + SW128(off + 64));
            }
#pragma unroll
            for (int mi = 0; mi < MI; mi++)
#pragma unroll
                for (int nj = 0; nj < 4; nj++) {
                    mma16816(acc[mi][nj * 2],     aq[mi], &bh[nj][0]);
                    mma16816(acc[mi][nj * 2 + 1], aq[mi], &bh[nj][2]);
                }
#pragma unroll
            for (int mi = 0; mi < MI; mi++)
#pragma unroll
                for (int nj = 0; nj < 4; nj++) {
                    mma16816(acc[mi][nj * 2],     aq[mi], &bl[nj][0]);
                    mma16816(acc[mi][nj * 2 + 1], aq[mi], &bl[nj][2]);
                }
        }
    }
}

// ===========================================================================
// Stage1: t1(hi) = u(hi) @ Up^T. grid (4 M-tiles, 64 N-groups), 256 thr.
// A (256x256 hi, 128KB) resident; loop over 8 N-tiles streaming B (SPLIT).
// smem: A 4x32KB + B 2x32KB = 192KB -> 1 CTA/SM.
// ===========================================================================
__global__ __launch_bounds__(256)
void stage1_k(const f16* __restrict__ U8, const f16* __restrict__ Up,
              f16* __restrict__ T1)
{
    extern __shared__ char dsm[];
    const uint32_t sraw = smem_u32(dsm);
    const uint32_t sb = (sraw + 1023u) & ~1023u;
    const uint32_t sbA = sb;
    const uint32_t sbB = sb + 131072;

    const int tid = threadIdx.x;
    const int lane = tid & 31;
    const int warp = tid >> 5;
    const int wm = warp >> 1, wn = warp & 1;
    const int aLB = ((lane & 15) * 128) + ((lane >> 4) * 16);
    const int bLB = (((lane & 7) + ((lane >> 4) << 3)) * 128) + (((lane >> 3) & 1) * 16);
    const int gRow = lane >> 2;
    const int cPair = (lane & 3) * 2;

    const f16* Au = U8 + (size_t)blockIdx.x * 256 * 512;

    auto bsrc = [&](int nt) {
        return Up + ((size_t)blockIdx.y * 8 + nt) * 65536;
    };
    auto issueU = [&](int u) {
        if (u < 32) {
            int nt = u >> 2, ch = u & 3;
            uint32_t buf = sbB + (u & 1) * 32768;
            const f16* Bb = bsrc(nt);
            load_split(Bb, 2 * ch,     buf,         tid);
            load_split(Bb, 2 * ch + 1, buf + 16384, tid);
        }
        CP_COMMIT();
    };

    // resident A: 4 PLAIN K64 tiles (grouped with unit 0's commit)
#pragma unroll
    for (int ch = 0; ch < 4; ch++)
        load_plain256(Au, 512, ch, sbA + ch * 32768, tid);
    issueU(0);
    issueU(1);

    float acc[4][8][4];
#pragma unroll
    for (int i = 0; i < 4; i++)
#pragma unroll
        for (int j = 0; j < 8; j++)
#pragma unroll
            for (int k = 0; k < 4; k++) acc[i][j][k] = 0.0f;

    for (int u = 0; u < 32; u++) {
        if (u < 31) CP_WAIT1(); else CP_WAIT0();
        __syncthreads();
        mma_unit<4, false>(sbB + (u & 1) * 32768, sbA + (u & 3) * 32768,
                           acc, aLB, bLB, wm, wn);
        if (u < 30) { __syncthreads(); issueU(u + 2); }

        if ((u & 3) == 3) {
            // epilogue for N-tile nt = u>>2 : hi-only f16 rows [t][65536]
            int nt = u >> 2;
            size_t colBase = ((size_t)blockIdx.y * 8 + nt) * 128;
#pragma unroll
            for (int mi = 0; mi < 4; mi++) {
                int rbase = blockIdx.x * 256 + wm * 64 + mi * 16 + gRow;
#pragma unroll
                for (int f = 0; f < 8; f++) {
                    int nloc = wn * 64 + f * 8 + cPair;
#pragma unroll
                    for (int hh = 0; hh < 2; hh++) {
                        size_t row = (size_t)(rbase + hh * 8);
                        __half2 p;
                        p.x = __float2half(acc[mi][f][hh * 2 + 0]);
                        p.y = __float2half(acc[mi][f][hh * 2 + 1]);
                        *(__half2*)(T1 + row * 65536 + colBase + nloc) = p;
                        acc[mi][f][hh * 2 + 0] = 0.0f;
                        acc[mi][f][hh * 2 + 1] = 0.0f;
                    }
                }
            }
        }
    }
}

// ===========================================================================
// Stage2/3 kernel: D[128,128] per (z, y). 4 K64 units, 2-deep, 2 CTAs/SM.
// SPLITA=1 (stage2): A split (hi|lo, rs 512), B plain (rs bRS).
// SPLITA=0 (stage3): A plain (rs aRS), B split (hi|lo, rs 512).
// EPI=0: hi-only f16 rows (stride cRS); EPI=1: f32 rows (stride 128).
// ===========================================================================
template <bool SPLITA, int EPI>
__global__ __launch_bounds__(256, 2)
void stage23_k(const f16* __restrict__ A, const f16* __restrict__ B,
               void* __restrict__ Cv,
               unsigned long long aBatch, int aShift, int aRS,
               unsigned long long bBatch, int bShift, int bRS,
               unsigned long long cBatch, int cRS)
{
    extern __shared__ char dsm[];
    const uint32_t sraw = smem_u32(dsm);
    const uint32_t sb = (sraw + 1023u) & ~1023u;

    const int tid = threadIdx.x;
    const int lane = tid & 31;
    const int warp = tid >> 5;
    const int wm = warp >> 1, wn = warp & 1;
    const int aLB = ((lane & 15) * 128) + ((lane >> 4) * 16);
    const int bLB = (((lane & 7) + ((lane >> 4) << 3)) * 128) + (((lane >> 3) & 1) * 16);
    const int gRow = lane >> 2;
    const int cPair = (lane & 3) * 2;
    const size_t z = blockIdx.z;

    const f16* Ab = A + (z >> aShift) * (size_t)aBatch;
    const f16* Bb = B + (z >> bShift) * (size_t)bBatch + (size_t)blockIdx.y * 128 * bRS;

    const f16* Xs = SPLITA ? Ab : Bb;   // split operand (rowstride 512)
    const f16* Ys = SPLITA ? Bb : Ab;   // plain operand
    const int  yRS = SPLITA ? bRS : aRS;

    auto issueU = [&](int u) {
        if (u < 4) {
            uint32_t buf = sb + (u & 1) * 49152;
            load_split(Xs, 2 * u,     buf,         tid);
            load_split(Xs, 2 * u + 1, buf + 16384, tid);
            load_plain(Ys, yRS, u,    buf + 32768, tid);
        }
        CP_COMMIT();
    };
    issueU(0);
    issueU(1);

    float acc[2][8][4];
#pragma unroll
    for (int i = 0; i < 2; i++)
#pragma unroll
        for (int j = 0; j < 8; j++)
#pragma unroll
            for (int k = 0; k < 4; k++) acc[i][j][k] = 0.0f;

#pragma unroll
    for (int u = 0; u < 4; u++) {
        if (u < 3) CP_WAIT1(); else CP_WAIT0();
        __syncthreads();
        uint32_t buf = sb + (u & 1) * 49152;
        mma_unit<2, SPLITA>(buf, buf + 32768, acc, aLB, bLB, wm, wn);
        if (u < 2) { __syncthreads(); issueU(u + 2); }
    }

    if (EPI == 0) {
        f16* Cb = (f16*)Cv + z * cBatch;
#pragma unroll
        for (int mi = 0; mi < 2; mi++) {
            int rbase = wm * 32 + mi * 16 + gRow;
#pragma unroll
            for (int f = 0; f < 8; f++) {
                int col = blockIdx.y * 128 + wn * 64 + f * 8 + cPair;
#pragma unroll
                for (int hh = 0; hh < 2; hh++) {
                    size_t row = (size_t)(rbase + hh * 8);
                    __half2 p;
                    p.x = __float2half(acc[mi][f][hh * 2 + 0]);
                    p.y = __float2half(acc[mi][f][hh * 2 + 1]);
                    *(__half2*)(Cb + row * cRS + col) = p;
                }
            }
        }
    } else {
        float* Cb = (float*)Cv + z * cBatch;
#pragma unroll
        for (int mi = 0; mi < 2; mi++) {
            int rbase = wm * 32 + mi * 16 + gRow;
#pragma unroll
            for (int f = 0; f < 8; f++) {
                int col = blockIdx.y * 128 + wn * 64 + f * 8 + cPair;
#pragma unroll
                for (int hh = 0; hh < 2; hh++) {
                    size_t row = (size_t)(rbase + hh * 8);
                    *(float2*)(Cb + row * 128 + col) =
                        make_float2(acc[mi][f][hh * 2 + 0], acc[mi][f][hh * 2 + 1]);
                }
            }
        }
    }
}

// ===========================================================================
// Projection GEMM (SIMT fp32): elu(h @ W + b) -> f16 hi|lo rows [1024,512]
// ===========================================================================
struct ProjArgs {
    const float* W[7];
    const float* bias[7];
};

__global__ __launch_bounds__(256, 2)
void proj_gemm(ProjArgs pa, const float* __restrict__ h, f16* __restrict__ outp)
{
    __shared__ float As[16][128];
    __shared__ float Bs[16][128];

    const int br = blockIdx.z;
    const float* A = h;
    const float* B = pa.W[br];
    const float* bias = pa.bias[br];

    const int tid = threadIdx.x;
    const int bm = blockIdx.y * 128;
    const int bn = blockIdx.x * 128;
    const int tx = tid & 15;
    const int ty = tid >> 4;

    float acc[8][8];
#pragma unroll
    for (int i = 0; i < 8; i++)
#pragma unroll
        for (int j = 0; j < 8; j++) acc[i][j] = 0.0f;

    for (int k0 = 0; k0 < 512; k0 += 16) {
#pragma unroll
        for (int i = 0; i < 2; i++) {
            int v = tid + i * 256;
            int r = v >> 2;
            int c4 = (v & 3) << 2;
            float4 a = *(const float4*)(A + (size_t)(bm + r) * 512 + k0 + c4);
            As[c4 + 0][r] = a.x; As[c4 + 1][r] = a.y;
            As[c4 + 2][r] = a.z; As[c4 + 3][r] = a.w;
        }
#pragma unroll
        for (int i = 0; i < 2; i++) {
            int v = tid + i * 256;
            int r = v >> 5;
            int c4 = (v & 31) << 2;
            float4 b = *(const float4*)(B + (size_t)(k0 + r) * 256 + bn + c4);
            *(float4*)&Bs[r][c4] = b;
        }
        __syncthreads();
#pragma unroll
        for (int kk = 0; kk < 16; kk++) {
            float ar[8], brg[8];
            *(float4*)&ar[0] = *(const float4*)&As[kk][ty * 8];
            *(float4*)&ar[4] = *(const float4*)&As[kk][ty * 8 + 4];
            *(float4*)&brg[0] = *(const float4*)&Bs[kk][tx * 8];
            *(float4*)&brg[4] = *(const float4*)&Bs[kk][tx * 8 + 4];
#pragma unroll
            for (int i = 0; i < 8; i++)
#pragma unroll
                for (int j = 0; j < 8; j++)
                    acc[i][j] = fmaf(ar[i], brg[j], acc[i][j]);
        }
        __syncthreads();
    }

    f16* Co = outp + (size_t)br * (1024 * 512);
#pragma unroll
    for (int i = 0; i < 8; i++) {
        int r = bm + ty * 8 + i;
#pragma unroll
        for (int j = 0; j < 8; j++) {
            int col = bn + tx * 8 + j;
            float v = acc[i][j] + bias[col];
            v = v > 0.f ? v : expm1f(v);
            f16 hb = __float2half(v);
            f16 lb = __float2half(v - __half2float(hb));
            Co[(size_t)r * 512 + col] = hb;
            Co[(size_t)r * 512 + 256 + col] = lb;
        }
    }
}

// ===========================================================================
// U permute+split: U[a,c,d] f32 -> Up[(d*256+c)][a] hi, [..][256+a] lo
// ===========================================================================
__global__ void uconv(const float* __restrict__ U, f16* __restrict__ Up)
{
    __shared__ float t[32][33];
    const int c = blockIdx.z;
    const int d0 = blockIdx.x * 32;
    const int a0 = blockIdx.y * 32;
    const int tx = threadIdx.x;
    const int ty = threadIdx.y;

#pragma unroll
    for (int i = 0; i < 32; i += 8)
        t[ty + i][tx] = U[(size_t)(a0 + ty + i) * 65536 + c * 256 + d0 + tx];
    __syncthreads();
#pragma unroll
    for (int i = 0; i < 32; i += 8) {
        int dl = ty + i;
        float v = t[tx][dl];
        f16 hb = __float2half(v);
        f16 lb = __float2half(v - __half2float(hb));
        size_t rowbase = ((size_t)(d0 + dl) * 256 + c) * 512;
        Up[rowbase + a0 + tx] = hb;
        Up[rowbase + 256 + a0 + tx] = lb;
    }
}

__global__ void build_h(const float* __restrict__ x, const float* __restrict__ sent,
                        float* __restrict__ h)
{
    int idx = blockIdx.x * blockDim.x + threadIdx.x;
    int rowi = idx >> 9;
    int e = idx & 511;
    int t = rowi & 127;
    int b = rowi >> 7;
    h[idx] = (t == 0) ? sent[e] : x[((size_t)(b * 127 + t - 1)) * 512 + e];
}

__global__ void write_mask(const int* __restrict__ mask, float* __restrict__ outm)
{
    int i = blockIdx.x * blockDim.x + threadIdx.x;
    if (i < 1024) {
        int b = i >> 7, t = i & 127;
        outm[i] = (t == 0) ? 1.0f : (float)mask[b * 127 + t - 1];
    }
}

// ===========================================================================
extern "C" void kernel_launch(void* const* d_in, const int* in_sizes, int n_in,
                              void* d_out, int out_size)
{
    (void)in_sizes; (void)n_in; (void)out_size;

    const float* x    = (const float*)d_in[0];
    const int*   mask = (const int*)d_in[2];
    const float* U[3] = { (const float*)d_in[17], (const float*)d_in[18], (const float*)d_in[19] };
    const float* sent = (const float*)d_in[20];
    float* out = (float*)d_out;

    float* h;
    f16 *projb, *Up, *t1, *t2;
    cudaGetSymbolAddress((void**)&h,     g_h);
    cudaGetSymbolAddress((void**)&projb, g_projb);
    cudaGetSymbolAddress((void**)&Up,    g_Up);
    cudaGetSymbolAddress((void**)&t1,    g_t1);
    cudaGetSymbolAddress((void**)&t2,    g_t2);

    const int SMEM1 = 131072 + 65536 + 1024;   // 197632, 1 CTA/SM
    const int SMEM23 = 2 * 49152 + 1024;       // 99328, 2 CTAs/SM
    cudaFuncSetAttribute(stage1_k, cudaFuncAttributeMaxDynamicSharedMemorySize, SMEM1);
    cudaFuncSetAttribute(stage23_k<true, 0>,  cudaFuncAttributeMaxDynamicSharedMemorySize, SMEM23);
    cudaFuncSetAttribute(stage23_k<false, 1>, cudaFuncAttributeMaxDynamicSharedMemorySize, SMEM23);

    ProjArgs pa;
    for (int i = 0; i < 7; i++) {
        pa.W[i]    = (const float*)d_in[3 + 2 * i];
        pa.bias[i] = (const float*)d_in[4 + 2 * i];
    }

    const size_t PB = 1024 * 512;
    const size_t UPS = (size_t)65536 * 512;
    const size_t T1S = (size_t)1024 * 65536;
    const int ui[3] = {0, 2, 4};
    const int vi[3] = {1, 3, 6};
    const int wi[3] = {1, 2, 5};

    auto stage1 = [&](int t) {
        stage1_k<<<dim3(4, 64), 256, SMEM1>>>(
            projb + ui[t] * PB, Up + t * UPS, t1 + t * T1S);
    };
    auto stage2 = [&](int t) {
        // A = v (split, per batch), B = t1 (plain, per bi), out t2 hi
        stage23_k<true, 0><<<dim3(1, 2, 1024), 256, SMEM23>>>(
            projb + vi[t] * PB, t1 + t * T1S, t2,
            65536ULL, 7, 512,
            65536ULL, 0, 256,
            32768ULL, 256);
    };
    auto stage3 = [&](int t) {
        // A = t2 (plain, per bi), B = w (split, per batch), out f32
        stage23_k<false, 1><<<dim3(1, 1, 1024), 256, SMEM23>>>(
            t2, projb + wi[t] * PB, out + (size_t)t * 16777216,
            32768ULL, 0, 256,
            65536ULL, 7, 512,
            16384ULL, 128);
    };

    // launch order: profiled slot (index 3) = stage1(0)
    build_h<<<2048, 256>>>(x, sent, h);                              // 0
    proj_gemm<<<dim3(2, 8, 7), 256>>>(pa, h, projb);                 // 1
    uconv<<<dim3(8, 8, 256), dim3(32, 8)>>>(U[0], Up + 0 * UPS);     // 2
    stage1(0);                                                       // 3 <- ncu
    uconv<<<dim3(8, 8, 256), dim3(32, 8)>>>(U[1], Up + 1 * UPS);
    uconv<<<dim3(8, 8, 256), dim3(32, 8)>>>(U[2], Up + 2 * UPS);
    stage1(1);
    stage1(2);
    stage2(0); stage3(0);
    stage2(1); stage3(1);
    stage2(2); stage3(2);
    write_mask<<<4, 256>>>(mask, out + (size_t)3 * 16777216);
}

// round 10
// speedup vs baseline: 1.7432x; 1.4934x over previous
#include <cuda_runtime.h>
#include <cuda_fp16.h>
#include <cstdint>
#include <math.h>

typedef __half f16;

// ===========================================================================
// TriParser, pure fp16 HMMA (f32 accum), single product per stage.
//   proj: elu(h@W+b) -> f16 rows [1024, 256]        (7 branches)
//   Up:   U[a,c,d]   -> f16 rows r=d*256+c, cols a  [65536, 256]
//   stage1: t1[bi][d][c] = u @ Up^T     (M-tile 256, A resident, N-loop)
//   stage2: t2[bi][j][d] = v[b] @ t1[bi]^T  (v resident, t1 streamed)
//   stage3: s[bi][j][k]  = t2[bi] @ w[b]^T  (f32 out)
// Error model: 6 fp16 rounding sources ~= 5e-4 rel (threshold 1e-3).
// ===========================================================================

__device__ float g_h[1024 * 512];                      // 2 MB
__device__ f16   g_projb[7 * 1024 * 256];              // 3.5 MB
__device__ f16   g_Up[3ull * 65536 * 256];             // 96 MB
__device__ f16   g_t1[3ull * 1024 * 65536];            // 402 MB
__device__ f16   g_t2[1024ull * 128 * 256];            // 67 MB

__device__ __forceinline__ uint32_t smem_u32(const void* p) {
    uint32_t a;
    asm("{ .reg .u64 t; cvta.to.shared.u64 t, %1; cvt.u32.u64 %0, t; }"
        : "=r"(a) : "l"(p));
    return a;
}

#define SW128(o) ((o) ^ (((o) >> 3) & 0x70))

__device__ __forceinline__ void ldm_x4(uint32_t* r, uint32_t addr) {
    asm volatile("ldmatrix.sync.aligned.m8n8.x4.shared.b16 {%0,%1,%2,%3}, [%4];"
                 : "=r"(r[0]), "=r"(r[1]), "=r"(r[2]), "=r"(r[3]) : "r"(addr));
}

__device__ __forceinline__ void mma16816(float* c, const uint32_t* a, const uint32_t* b) {
    asm volatile(
        "mma.sync.aligned.m16n8k16.row.col.f32.f16.f16.f32 "
        "{%0,%1,%2,%3}, {%4,%5,%6,%7}, {%8,%9}, {%0,%1,%2,%3};"
        : "+f"(c[0]), "+f"(c[1]), "+f"(c[2]), "+f"(c[3])
        : "r"(a[0]), "r"(a[1]), "r"(a[2]), "r"(a[3]), "r"(b[0]), "r"(b[1]));
}

__device__ __forceinline__ void cpa16(uint32_t dst, const void* src) {
    asm volatile("cp.async.cg.shared.global [%0], [%1], 16;" :: "r"(dst), "l"(src) : "memory");
}
#define CP_COMMIT() asm volatile("cp.async.commit_group;" ::: "memory")
#define CP_WAIT1()  asm volatile("cp.async.wait_group 1;" ::: "memory")
#define CP_WAIT0()  asm volatile("cp.async.wait_group 0;" ::: "memory")

// PLAIN K64 tile, 128 rows (16KB): rows x 128B, SW128. src rowstride rs f16.
__device__ __forceinline__ void load_plain(const f16* __restrict__ g, int rs, int c64,
                                           uint32_t dst, int tid) {
#pragma unroll
    for (int i = 0; i < 4; i++) {
        int idx = tid + i * 256;
        int row = idx >> 3, seg = idx & 7;
        cpa16(dst + SW128(row * 128 + seg * 16), g + (size_t)row * rs + c64 * 64 + seg * 8);
    }
}

// PLAIN K64 tile, 256 rows (32KB), stage1 resident A.
__device__ __forceinline__ void load_plain256(const f16* __restrict__ g, int rs, int c64,
                                              uint32_t dst, int tid) {
#pragma unroll
    for (int i = 0; i < 8; i++) {
        int idx = tid + i * 256;
        int row = idx >> 3, seg = idx & 7;
        cpa16(dst + SW128(row * 128 + seg * 16), g + (size_t)row * rs + c64 * 64 + seg * 8);
    }
}

// One K64 unit: D[(MI*16*wmN) x 128] += A @ B^T, plain operands.
// A tile at ab (rows = M), B tile at bb (128 rows).
template <int MI>
__device__ __forceinline__ void mma_unit(uint32_t ab, uint32_t bb,
                                         float (&acc)[MI][8][4],
                                         int aLB, int bLB, int wm, int wn) {
#pragma unroll
    for (int kk = 0; kk < 4; kk++) {
        uint32_t aq[MI][4], bq[4][4];
#pragma unroll
        for (int mi = 0; mi < MI; mi++) {
            int off = aLB + (wm * (MI * 16) + mi * 16) * 128 + kk * 32;
            ldm_x4(aq[mi], ab + SW128(off));
        }
#pragma unroll
        for (int nj = 0; nj < 4; nj++) {
            int off = bLB + (wn * 64 + nj * 16) * 128 + kk * 32;
            ldm_x4(bq[nj], bb + SW128(off));
        }
#pragma unroll
        for (int mi = 0; mi < MI; mi++)
#pragma unroll
            for (int nj = 0; nj < 4; nj++) {
                mma16816(acc[mi][nj * 2],     aq[mi], &bq[nj][0]);
                mma16816(acc[mi][nj * 2 + 1], aq[mi], &bq[nj][2]);
            }
    }
}

// ===========================================================================
// Stage1: t1 = u @ Up^T. grid (4 M-tiles, 64 N-groups), 256 thr, 1 CTA/SM.
// A (256x256, 128KB) resident; 8 N-tiles x 4 K64 units, B 2x16KB stream.
// ===========================================================================
__global__ __launch_bounds__(256)
void stage1_k(const f16* __restrict__ U8, const f16* __restrict__ Up,
              f16* __restrict__ T1)
{
    extern __shared__ char dsm[];
    const uint32_t sraw = smem_u32(dsm);
    const uint32_t sb = (sraw + 1023u) & ~1023u;
    const uint32_t sbA = sb;
    const uint32_t sbB = sb + 131072;

    const int tid = threadIdx.x;
    const int lane = tid & 31;
    const int warp = tid >> 5;
    const int wm = warp >> 1, wn = warp & 1;
    const int aLB = ((lane & 15) * 128) + ((lane >> 4) * 16);
    const int bLB = (((lane & 7) + ((lane >> 4) << 3)) * 128) + (((lane >> 3) & 1) * 16);
    const int gRow = lane >> 2;
    const int cPair = (lane & 3) * 2;

    const f16* Au = U8 + (size_t)blockIdx.x * 256 * 256;

    auto bsrc = [&](int nt) {
        return Up + ((size_t)blockIdx.y * 8 + nt) * 128 * 256;
    };
    auto issueU = [&](int u) {
        if (u < 32) {
            int nt = u >> 2, ch = u & 3;
            load_plain(bsrc(nt), 256, ch, sbB + (u & 1) * 16384, tid);
        }
        CP_COMMIT();
    };

    // resident A: 4 PLAIN K64 tiles (256 rows), grouped with unit0 commit
#pragma unroll
    for (int ch = 0; ch < 4; ch++)
        load_plain256(Au, 256, ch, sbA + ch * 32768, tid);
    issueU(0);
    issueU(1);

    float acc[4][8][4];
#pragma unroll
    for (int i = 0; i < 4; i++)
#pragma unroll
        for (int j = 0; j < 8; j++)
#pragma unroll
            for (int k = 0; k < 4; k++) acc[i][j][k] = 0.0f;

    for (int u = 0; u < 32; u++) {
        if (u < 31) CP_WAIT1(); else CP_WAIT0();
        __syncthreads();
        mma_unit<4>(sbA + (u & 3) * 32768, sbB + (u & 1) * 16384,
                    acc, aLB, bLB, wm, wn);
        if (u < 30) { __syncthreads(); issueU(u + 2); }

        if ((u & 3) == 3) {
            int nt = u >> 2;
            size_t colBase = ((size_t)blockIdx.y * 8 + nt) * 128;
#pragma unroll
            for (int mi = 0; mi < 4; mi++) {
                int rbase = blockIdx.x * 256 + wm * 64 + mi * 16 + gRow;
#pragma unroll
                for (int f = 0; f < 8; f++) {
                    int nloc = wn * 64 + f * 8 + cPair;
#pragma unroll
                    for (int hh = 0; hh < 2; hh++) {
                        size_t row = (size_t)(rbase + hh * 8);
                        __half2 p;
                        p.x = __float2half(acc[mi][f][hh * 2 + 0]);
                        p.y = __float2half(acc[mi][f][hh * 2 + 1]);
                        *(__half2*)(T1 + row * 65536 + colBase + nloc) = p;
                        acc[mi][f][hh * 2 + 0] = 0.0f;
                        acc[mi][f][hh * 2 + 1] = 0.0f;
                    }
                }
            }
        }
    }
}

// ===========================================================================
// Stage2/3: per token z. A [128,256] resident (64KB); B streamed (2x16KB).
// NH N-halves of 128 cols each. EPI=0 f16 out (rs cRS); EPI=1 f32 out (rs 128).
// 96KB smem + acc 64 regs -> 2 CTAs/SM.
// ===========================================================================
template <int NH, int EPI>
__global__ __launch_bounds__(256, 2)
void stage23_k(const f16* __restrict__ A, unsigned long long aBatch, int aShift,
               const f16* __restrict__ B, unsigned long long bBatch, int bShift,
               void* __restrict__ Cv, unsigned long long cBatch, int cRS)
{
    extern __shared__ char dsm[];
    const uint32_t sraw = smem_u32(dsm);
    const uint32_t sb = (sraw + 1023u) & ~1023u;
    const uint32_t sbA = sb;
    const uint32_t sbB = sb + 65536;

    const int tid = threadIdx.x;
    const int lane = tid & 31;
    const int warp = tid >> 5;
    const int wm = warp >> 1, wn = warp & 1;
    const int aLB = ((lane & 15) * 128) + ((lane >> 4) * 16);
    const int bLB = (((lane & 7) + ((lane >> 4) << 3)) * 128) + (((lane >> 3) & 1) * 16);
    const int gRow = lane >> 2;
    const int cPair = (lane & 3) * 2;
    const size_t z = blockIdx.x;

    const f16* Ab = A + (z >> aShift) * (size_t)aBatch;
    const f16* Bb = B + (z >> bShift) * (size_t)bBatch;

    auto issueU = [&](int g) {
        if (g < NH * 4) {
            int nh = g >> 2, ch = g & 3;
            load_plain(Bb + (size_t)nh * 128 * 256, 256, ch, sbB + (g & 1) * 16384, tid);
        }
        CP_COMMIT();
    };

#pragma unroll
    for (int ch = 0; ch < 4; ch++)
        load_plain(Ab, 256, ch, sbA + ch * 16384, tid);
    issueU(0);
    issueU(1);

    float acc[2][8][4];
#pragma unroll
    for (int i = 0; i < 2; i++)
#pragma unroll
        for (int j = 0; j < 8; j++)
#pragma unroll
            for (int k = 0; k < 4; k++) acc[i][j][k] = 0.0f;

#pragma unroll
    for (int g = 0; g < NH * 4; g++) {
        if (g < NH * 4 - 1) CP_WAIT1(); else CP_WAIT0();
        __syncthreads();
        mma_unit<2>(sbA + (g & 3) * 16384, sbB + (g & 1) * 16384,
                    acc, aLB, bLB, wm, wn);
        if (g < NH * 4 - 2) { __syncthreads(); issueU(g + 2); }

        if ((g & 3) == 3) {
            int nh = g >> 2;
#pragma unroll
            for (int mi = 0; mi < 2; mi++) {
                int rbase = wm * 32 + mi * 16 + gRow;
#pragma unroll
                for (int f = 0; f < 8; f++) {
                    int col = nh * 128 + wn * 64 + f * 8 + cPair;
#pragma unroll
                    for (int hh = 0; hh < 2; hh++) {
                        size_t row = (size_t)(rbase + hh * 8);
                        if (EPI == 0) {
                            __half2 p;
                            p.x = __float2half(acc[mi][f][hh * 2 + 0]);
                            p.y = __float2half(acc[mi][f][hh * 2 + 1]);
                            *(__half2*)((f16*)Cv + z * cBatch + row * cRS + col) = p;
                        } else {
                            *(float2*)((float*)Cv + z * cBatch + row * 128 + col) =
                                make_float2(acc[mi][f][hh * 2 + 0], acc[mi][f][hh * 2 + 1]);
                        }
                        acc[mi][f][hh * 2 + 0] = 0.0f;
                        acc[mi][f][hh * 2 + 1] = 0.0f;
                    }
                }
            }
        }
    }
}

// ===========================================================================
// Projection GEMM (SIMT fp32): elu(h @ W + b) -> f16 rows [1024,256]
// ===========================================================================
struct ProjArgs {
    const float* W[7];
    const float* bias[7];
};

__global__ __launch_bounds__(256, 2)
void proj_gemm(ProjArgs pa, const float* __restrict__ h, f16* __restrict__ outp)
{
    __shared__ float As[16][128];
    __shared__ float Bs[16][128];

    const int br = blockIdx.z;
    const float* A = h;
    const float* B = pa.W[br];
    const float* bias = pa.bias[br];

    const int tid = threadIdx.x;
    const int bm = blockIdx.y * 128;
    const int bn = blockIdx.x * 128;
    const int tx = tid & 15;
    const int ty = tid >> 4;

    float acc[8][8];
#pragma unroll
    for (int i = 0; i < 8; i++)
#pragma unroll
        for (int j = 0; j < 8; j++) acc[i][j] = 0.0f;

    for (int k0 = 0; k0 < 512; k0 += 16) {
#pragma unroll
        for (int i = 0; i < 2; i++) {
            int v = tid + i * 256;
            int r = v >> 2;
            int c4 = (v & 3) << 2;
            float4 a = *(const float4*)(A + (size_t)(bm + r) * 512 + k0 + c4);
            As[c4 + 0][r] = a.x; As[c4 + 1][r] = a.y;
            As[c4 + 2][r] = a.z; As[c4 + 3][r] = a.w;
        }
#pragma unroll
        for (int i = 0; i < 2; i++) {
            int v = tid + i * 256;
            int r = v >> 5;
            int c4 = (v & 31) << 2;
            float4 b = *(const float4*)(B + (size_t)(k0 + r) * 256 + bn + c4);
            *(float4*)&Bs[r][c4] = b;
        }
        __syncthreads();
#pragma unroll
        for (int kk = 0; kk < 16; kk++) {
            float ar[8], brg[8];
            *(float4*)&ar[0] = *(const float4*)&As[kk][ty * 8];
            *(float4*)&ar[4] = *(const float4*)&As[kk][ty * 8 + 4];
            *(float4*)&brg[0] = *(const float4*)&Bs[kk][tx * 8];
            *(float4*)&brg[4] = *(const float4*)&Bs[kk][tx * 8 + 4];
#pragma unroll
            for (int i = 0; i < 8; i++)
#pragma unroll
                for (int j = 0; j < 8; j++)
                    acc[i][j] = fmaf(ar[i], brg[j], acc[i][j]);
        }
        __syncthreads();
    }

    f16* Co = outp + (size_t)br * (1024 * 256);
#pragma unroll
    for (int i = 0; i < 8; i++) {
        int r = bm + ty * 8 + i;
#pragma unroll
        for (int j = 0; j < 8; j++) {
            int col = bn + tx * 8 + j;
            float v = acc[i][j] + bias[col];
            v = v > 0.f ? v : expm1f(v);
            Co[(size_t)r * 256 + col] = __float2half(v);
        }
    }
}

// ===========================================================================
// U permute: U[a,c,d] f32 -> Up[(d*256+c)][a] f16
// ===========================================================================
__global__ void uconv(const float* __restrict__ U, f16* __restrict__ Up)
{
    __shared__ float t[32][33];
    const int c = blockIdx.z;
    const int d0 = blockIdx.x * 32;
    const int a0 = blockIdx.y * 32;
    const int tx = threadIdx.x;
    const int ty = threadIdx.y;

#pragma unroll
    for (int i = 0; i < 32; i += 8)
        t[ty + i][tx] = U[(size_t)(a0 + ty + i) * 65536 + c * 256 + d0 + tx];
    __syncthreads();
#pragma unroll
    for (int i = 0; i < 32; i += 8) {
        int dl = ty + i;
        size_t rowbase = ((size_t)(d0 + dl) * 256 + c) * 256;
        Up[rowbase + a0 + tx] = __float2half(t[tx][dl]);
    }
}

__global__ void build_h(const float* __restrict__ x, const float* __restrict__ sent,
                        float* __restrict__ h)
{
    int idx = blockIdx.x * blockDim.x + threadIdx.x;
    int rowi = idx >> 9;
    int e = idx & 511;
    int t = rowi & 127;
    int b = rowi >> 7;
    h[idx] = (t == 0) ? sent[e] : x[((size_t)(b * 127 + t - 1)) * 512 + e];
}

__global__ void write_mask(const int* __restrict__ mask, float* __restrict__ outm)
{
    int i = blockIdx.x * blockDim.x + threadIdx.x;
    if (i < 1024) {
        int b = i >> 7, t = i & 127;
        outm[i] = (t == 0) ? 1.0f : (float)mask[b * 127 + t - 1];
    }
}

// ===========================================================================
extern "C" void kernel_launch(void* const* d_in, const int* in_sizes, int n_in,
                              void* d_out, int out_size)
{
    (void)in_sizes; (void)n_in; (void)out_size;

    const float* x    = (const float*)d_in[0];
    const int*   mask = (const int*)d_in[2];
    const float* U[3] = { (const float*)d_in[17], (const float*)d_in[18], (const float*)d_in[19] };
    const float* sent = (const float*)d_in[20];
    float* out = (float*)d_out;

    float* h;
    f16 *projb, *Up, *t1, *t2;
    cudaGetSymbolAddress((void**)&h,     g_h);
    cudaGetSymbolAddress((void**)&projb, g_projb);
    cudaGetSymbolAddress((void**)&Up,    g_Up);
    cudaGetSymbolAddress((void**)&t1,    g_t1);
    cudaGetSymbolAddress((void**)&t2,    g_t2);

    const int SMEM1  = 131072 + 2 * 16384 + 1024;  // 164864, 1 CTA/SM
    const int SMEM23 = 65536 + 2 * 16384 + 1024;   // 99328, 2 CTAs/SM
    cudaFuncSetAttribute(stage1_k, cudaFuncAttributeMaxDynamicSharedMemorySize, SMEM1);
    cudaFuncSetAttribute(stage23_k<2, 0>, cudaFuncAttributeMaxDynamicSharedMemorySize, SMEM23);
    cudaFuncSetAttribute(stage23_k<1, 1>, cudaFuncAttributeMaxDynamicSharedMemorySize, SMEM23);

    ProjArgs pa;
    for (int i = 0; i < 7; i++) {
        pa.W[i]    = (const float*)d_in[3 + 2 * i];
        pa.bias[i] = (const float*)d_in[4 + 2 * i];
    }

    const size_t PB = 1024 * 256;
    const size_t UPS = (size_t)65536 * 256;
    const size_t T1S = (size_t)1024 * 65536;
    const int ui[3] = {0, 2, 4};
    const int vi[3] = {1, 3, 6};
    const int wi[3] = {1, 2, 5};

    auto stage1 = [&](int t) {
        stage1_k<<<dim3(4, 64), 256, SMEM1>>>(
            projb + ui[t] * PB, Up + t * UPS, t1 + t * T1S);
    };
    auto stage2 = [&](int t) {
        // A = v[b] (resident), B = t1[bi] [256 d, 256 c], out t2 [128 j, 256 d]
        stage23_k<2, 0><<<1024, 256, SMEM23>>>(
            projb + vi[t] * PB, 32768ULL, 7,
            t1 + t * T1S, 65536ULL, 0,
            t2, 32768ULL, 256);
    };
    auto stage3 = [&](int t) {
        // A = t2[bi] (resident), B = w[b] [128 k, 256 d], out f32 [128 j, 128 k]
        stage23_k<1, 1><<<1024, 256, SMEM23>>>(
            t2, 32768ULL, 0,
            projb + wi[t] * PB, 32768ULL, 7,
            out + (size_t)t * 16777216, 16384ULL, 128);
    };

    // launch order: profiled slot (index 3) = stage1(0)
    build_h<<<2048, 256>>>(x, sent, h);                              // 0
    proj_gemm<<<dim3(2, 8, 7), 256>>>(pa, h, projb);                 // 1
    uconv<<<dim3(8, 8, 256), dim3(32, 8)>>>(U[0], Up + 0 * UPS);     // 2
    stage1(0);                                                       // 3 <- ncu
    uconv<<<dim3(8, 8, 256), dim3(32, 8)>>>(U[1], Up + 1 * UPS);
    uconv<<<dim3(8, 8, 256), dim3(32, 8)>>>(U[2], Up + 2 * UPS);
    stage1(1);
    stage1(2);
    stage2(0); stage3(0);
    stage2(1); stage3(1);
    stage2(2); stage3(2);
    write_mask<<<4, 256>>>(mask, out + (size_t)3 * 16777216);
}

// round 11
// speedup vs baseline: 1.8158x; 1.0417x over previous
#include <cuda_runtime.h>
#include <cuda_fp16.h>
#include <cstdint>
#include <math.h>

typedef __half f16;

// ===========================================================================
// TriParser, pure fp16 HMMA (f32 accum), single product per stage.
//   proj: elu(h@W+b) -> f16 rows [1024, 256]        (7 branches)
//   Up:   U[a,c,d]   -> f16 rows r=d*256+c, cols a  [65536, 256]
//   stage1: t1[bi][d][c] = u @ Up^T     (M-tile 128, A resident, 2 CTA/SM)
//   stage2: t2[bi][j][d] = v[b] @ t1[bi]^T
//   stage3: s[bi][j][k]  = t2[bi] @ w[b]^T  (f32 out)
// All three tris merged per stage launch (grid z/y = tri).
// ===========================================================================

__device__ float g_h[1024 * 512];                      // 2 MB
__device__ f16   g_projb[7 * 1024 * 256];              // 3.5 MB
__device__ f16   g_Up[3ull * 65536 * 256];             // 96 MB
__device__ f16   g_t1[3ull * 1024 * 65536];            // 402 MB
__device__ f16   g_t2[3ull * 1024 * 128 * 256];        // 201 MB

static const size_t PB  = 1024 * 256;
static const size_t UPS = (size_t)65536 * 256;
static const size_t T1S = (size_t)1024 * 65536;
static const size_t T2S = (size_t)1024 * 32768;

__device__ __forceinline__ uint32_t smem_u32(const void* p) {
    uint32_t a;
    asm("{ .reg .u64 t; cvta.to.shared.u64 t, %1; cvt.u32.u64 %0, t; }"
        : "=r"(a) : "l"(p));
    return a;
}

#define SW128(o) ((o) ^ (((o) >> 3) & 0x70))

__device__ __forceinline__ void ldm_x4(uint32_t* r, uint32_t addr) {
    asm volatile("ldmatrix.sync.aligned.m8n8.x4.shared.b16 {%0,%1,%2,%3}, [%4];"
                 : "=r"(r[0]), "=r"(r[1]), "=r"(r[2]), "=r"(r[3]) : "r"(addr));
}

__device__ __forceinline__ void mma16816(float* c, const uint32_t* a, const uint32_t* b) {
    asm volatile(
        "mma.sync.aligned.m16n8k16.row.col.f32.f16.f16.f32 "
        "{%0,%1,%2,%3}, {%4,%5,%6,%7}, {%8,%9}, {%0,%1,%2,%3};"
        : "+f"(c[0]), "+f"(c[1]), "+f"(c[2]), "+f"(c[3])
        : "r"(a[0]), "r"(a[1]), "r"(a[2]), "r"(a[3]), "r"(b[0]), "r"(b[1]));
}

__device__ __forceinline__ void cpa16(uint32_t dst, const void* src) {
    asm volatile("cp.async.cg.shared.global [%0], [%1], 16;" :: "r"(dst), "l"(src) : "memory");
}
#define CP_COMMIT() asm volatile("cp.async.commit_group;" ::: "memory")
#define CP_WAIT1()  asm volatile("cp.async.wait_group 1;" ::: "memory")
#define CP_WAIT0()  asm volatile("cp.async.wait_group 0;" ::: "memory")

// PLAIN K64 tile, 128 rows (16KB): rows x 128B, SW128. src rowstride rs f16.
__device__ __forceinline__ void load_plain(const f16* __restrict__ g, int rs, int c64,
                                           uint32_t dst, int tid) {
#pragma unroll
    for (int i = 0; i < 4; i++) {
        int idx = tid + i * 256;
        int row = idx >> 3, seg = idx & 7;
        cpa16(dst + SW128(row * 128 + seg * 16), g + (size_t)row * rs + c64 * 64 + seg * 8);
    }
}

// One K64 unit: D[32 x 128] per warp, plain operands (A at ab, B at bb).
__device__ __forceinline__ void mma_unit(uint32_t ab, uint32_t bb,
                                         float (&acc)[2][8][4],
                                         int aLB, int bLB, int wm, int wn) {
#pragma unroll
    for (int kk = 0; kk < 4; kk++) {
        uint32_t aq[2][4], bq[4][4];
#pragma unroll
        for (int mi = 0; mi < 2; mi++) {
            int off = aLB + (wm * 32 + mi * 16) * 128 + kk * 32;
            ldm_x4(aq[mi], ab + SW128(off));
        }
#pragma unroll
        for (int nj = 0; nj < 4; nj++) {
            int off = bLB + (wn * 64 + nj * 16) * 128 + kk * 32;
            ldm_x4(bq[nj], bb + SW128(off));
        }
#pragma unroll
        for (int mi = 0; mi < 2; mi++)
#pragma unroll
            for (int nj = 0; nj < 4; nj++) {
                mma16816(acc[mi][nj * 2],     aq[mi], &bq[nj][0]);
                mma16816(acc[mi][nj * 2 + 1], aq[mi], &bq[nj][2]);
            }
    }
}

#define ZERO_ACC(acc) \
    { _Pragma("unroll") for (int i = 0; i < 2; i++) \
      _Pragma("unroll") for (int j = 0; j < 8; j++) \
      _Pragma("unroll") for (int k = 0; k < 4; k++) acc[i][j][k] = 0.0f; }

// ===========================================================================
// Stage1 (all tris): t1 = u @ Up^T. grid (8 M, 64 Ngrp, 3 tri), 2 CTA/SM.
// A [128x256] resident (64KB); 8 N-tiles x 4 K64 units, B 2x16KB stream.
// ===========================================================================
__global__ __launch_bounds__(256, 2)
void stage1_k(const f16* __restrict__ projb, const f16* __restrict__ Up,
              f16* __restrict__ T1)
{
    extern __shared__ char dsm[];
    const uint32_t sraw = smem_u32(dsm);
    const uint32_t sb = (sraw + 1023u) & ~1023u;
    const uint32_t sbA = sb;
    const uint32_t sbB = sb + 65536;

    const int tid = threadIdx.x;
    const int lane = tid & 31;
    const int warp = tid >> 5;
    const int wm = warp >> 1, wn = warp & 1;
    const int aLB = ((lane & 15) * 128) + ((lane >> 4) * 16);
    const int bLB = (((lane & 7) + ((lane >> 4) << 3)) * 128) + (((lane >> 3) & 1) * 16);
    const int gRow = lane >> 2;
    const int cPair = (lane & 3) * 2;

    const int tri = blockIdx.z;
    const f16* Au  = projb + (size_t)(2 * tri) * PB + (size_t)blockIdx.x * 128 * 256;
    const f16* Ub  = Up + (size_t)tri * UPS;
    f16* T1t = T1 + (size_t)tri * T1S;

    auto issueU = [&](int u) {
        if (u < 32) {
            int nt = u >> 2, ch = u & 3;
            load_plain(Ub + ((size_t)blockIdx.y * 8 + nt) * 128 * 256, 256, ch,
                       sbB + (u & 1) * 16384, tid);
        }
        CP_COMMIT();
    };

#pragma unroll
    for (int ch = 0; ch < 4; ch++)
        load_plain(Au, 256, ch, sbA + ch * 16384, tid);
    issueU(0);
    issueU(1);

    float acc[2][8][4];
    ZERO_ACC(acc);

    for (int u = 0; u < 32; u++) {
        if (u < 31) CP_WAIT1(); else CP_WAIT0();
        __syncthreads();
        mma_unit(sbA + (u & 3) * 16384, sbB + (u & 1) * 16384, acc, aLB, bLB, wm, wn);
        if (u < 30) { __syncthreads(); issueU(u + 2); }

        if ((u & 3) == 3) {
            int nt = u >> 2;
            size_t colBase = ((size_t)blockIdx.y * 8 + nt) * 128;
#pragma unroll
            for (int mi = 0; mi < 2; mi++) {
                int rbase = blockIdx.x * 128 + wm * 32 + mi * 16 + gRow;
#pragma unroll
                for (int f = 0; f < 8; f++) {
                    int nloc = wn * 64 + f * 8 + cPair;
#pragma unroll
                    for (int hh = 0; hh < 2; hh++) {
                        size_t row = (size_t)(rbase + hh * 8);
                        __half2 p;
                        p.x = __float2half(acc[mi][f][hh * 2 + 0]);
                        p.y = __float2half(acc[mi][f][hh * 2 + 1]);
                        *(__half2*)(T1t + row * 65536 + colBase + nloc) = p;
                        acc[mi][f][hh * 2 + 0] = 0.0f;
                        acc[mi][f][hh * 2 + 1] = 0.0f;
                    }
                }
            }
        }
    }
}

// ===========================================================================
// Stage2/3 (all tris): per (token z, tri y). A [128,256] resident; B streamed.
// NH N-halves of 128 cols. EPI=0 f16 out (rs cRS); EPI=1 f32 out (rs 128).
// ===========================================================================
struct Ptr3 { const f16* p[3]; };

template <int NH, int EPI>
__global__ __launch_bounds__(256, 2)
void stage23_k(Ptr3 Ap, unsigned long long aBatch, int aShift,
               Ptr3 Bp, unsigned long long bBatch, int bShift,
               void* __restrict__ Cv, unsigned long long cTri,
               unsigned long long cBatch, int cRS)
{
    extern __shared__ char dsm[];
    const uint32_t sraw = smem_u32(dsm);
    const uint32_t sb = (sraw + 1023u) & ~1023u;
    const uint32_t sbA = sb;
    const uint32_t sbB = sb + 65536;

    const int tid = threadIdx.x;
    const int lane = tid & 31;
    const int warp = tid >> 5;
    const int wm = warp >> 1, wn = warp & 1;
    const int aLB = ((lane & 15) * 128) + ((lane >> 4) * 16);
    const int bLB = (((lane & 7) + ((lane >> 4) << 3)) * 128) + (((lane >> 3) & 1) * 16);
    const int gRow = lane >> 2;
    const int cPair = (lane & 3) * 2;

    const size_t z = blockIdx.x;
    const int tri = blockIdx.y;
    const f16* Ab = Ap.p[tri] + (z >> aShift) * (size_t)aBatch;
    const f16* Bb = Bp.p[tri] + (z >> bShift) * (size_t)bBatch;

    auto issueU = [&](int g) {
        if (g < NH * 4) {
            int nh = g >> 2, ch = g & 3;
            load_plain(Bb + (size_t)nh * 128 * 256, 256, ch, sbB + (g & 1) * 16384, tid);
        }
        CP_COMMIT();
    };

#pragma unroll
    for (int ch = 0; ch < 4; ch++)
        load_plain(Ab, 256, ch, sbA + ch * 16384, tid);
    issueU(0);
    issueU(1);

    float acc[2][8][4];
    ZERO_ACC(acc);

#pragma unroll
    for (int g = 0; g < NH * 4; g++) {
        if (g < NH * 4 - 1) CP_WAIT1(); else CP_WAIT0();
        __syncthreads();
        mma_unit(sbA + (g & 3) * 16384, sbB + (g & 1) * 16384, acc, aLB, bLB, wm, wn);
        if (g < NH * 4 - 2) { __syncthreads(); issueU(g + 2); }

        if ((g & 3) == 3) {
            int nh = g >> 2;
#pragma unroll
            for (int mi = 0; mi < 2; mi++) {
                int rbase = wm * 32 + mi * 16 + gRow;
#pragma unroll
                for (int f = 0; f < 8; f++) {
                    int col = nh * 128 + wn * 64 + f * 8 + cPair;
#pragma unroll
                    for (int hh = 0; hh < 2; hh++) {
                        size_t row = (size_t)(rbase + hh * 8);
                        if (EPI == 0) {
                            __half2 p;
                            p.x = __float2half(acc[mi][f][hh * 2 + 0]);
                            p.y = __float2half(acc[mi][f][hh * 2 + 1]);
                            *(__half2*)((f16*)Cv + tri * cTri + z * cBatch + row * cRS + col) = p;
                        } else {
                            *(float2*)((float*)Cv + tri * cTri + z * cBatch + row * 128 + col) =
                                make_float2(acc[mi][f][hh * 2 + 0], acc[mi][f][hh * 2 + 1]);
                        }
                        acc[mi][f][hh * 2 + 0] = 0.0f;
                        acc[mi][f][hh * 2 + 1] = 0.0f;
                    }
                }
            }
        }
    }
}

// ===========================================================================
// Projection GEMM (SIMT fp32): elu(h @ W + b) -> f16 rows [1024,256]
// ===========================================================================
struct ProjArgs {
    const float* W[7];
    const float* bias[7];
};

__global__ __launch_bounds__(256, 2)
void proj_gemm(ProjArgs pa, const float* __restrict__ h, f16* __restrict__ outp)
{
    __shared__ float As[16][128];
    __shared__ float Bs[16][128];

    const int br = blockIdx.z;
    const float* A = h;
    const float* B = pa.W[br];
    const float* bias = pa.bias[br];

    const int tid = threadIdx.x;
    const int bm = blockIdx.y * 128;
    const int bn = blockIdx.x * 128;
    const int tx = tid & 15;
    const int ty = tid >> 4;

    float acc[8][8];
#pragma unroll
    for (int i = 0; i < 8; i++)
#pragma unroll
        for (int j = 0; j < 8; j++) acc[i][j] = 0.0f;

    for (int k0 = 0; k0 < 512; k0 += 16) {
#pragma unroll
        for (int i = 0; i < 2; i++) {
            int v = tid + i * 256;
            int r = v >> 2;
            int c4 = (v & 3) << 2;
            float4 a = *(const float4*)(A + (size_t)(bm + r) * 512 + k0 + c4);
            As[c4 + 0][r] = a.x; As[c4 + 1][r] = a.y;
            As[c4 + 2][r] = a.z; As[c4 + 3][r] = a.w;
        }
#pragma unroll
        for (int i = 0; i < 2; i++) {
            int v = tid + i * 256;
            int r = v >> 5;
            int c4 = (v & 31) << 2;
            float4 b = *(const float4*)(B + (size_t)(k0 + r) * 256 + bn + c4);
            *(float4*)&Bs[r][c4] = b;
        }
        __syncthreads();
#pragma unroll
        for (int kk = 0; kk < 16; kk++) {
            float ar[8], brg[8];
            *(float4*)&ar[0] = *(const float4*)&As[kk][ty * 8];
            *(float4*)&ar[4] = *(const float4*)&As[kk][ty * 8 + 4];
            *(float4*)&brg[0] = *(const float4*)&Bs[kk][tx * 8];
            *(float4*)&brg[4] = *(const float4*)&Bs[kk][tx * 8 + 4];
#pragma unroll
            for (int i = 0; i < 8; i++)
#pragma unroll
                for (int j = 0; j < 8; j++)
                    acc[i][j] = fmaf(ar[i], brg[j], acc[i][j]);
        }
        __syncthreads();
    }

    f16* Co = outp + (size_t)br * (1024 * 256);
#pragma unroll
    for (int i = 0; i < 8; i++) {
        int r = bm + ty * 8 + i;
#pragma unroll
        for (int j = 0; j < 8; j++) {
            int col = bn + tx * 8 + j;
            float v = acc[i][j] + bias[col];
            v = v > 0.f ? v : expm1f(v);
            Co[(size_t)r * 256 + col] = __float2half(v);
        }
    }
}

// ===========================================================================
// U permute (all tris): U[a,c,d] f32 -> Up[(d*256+c)][a] f16
// ===========================================================================
struct PtrU { const float* p[3]; };

__global__ void uconv(PtrU Us, f16* __restrict__ Up)
{
    __shared__ float t[32][33];
    const int zz = blockIdx.z;
    const int tri = zz >> 8;
    const int c = zz & 255;
    const float* U = Us.p[tri];
    f16* Upt = Up + (size_t)tri * UPS;
    const int d0 = blockIdx.x * 32;
    const int a0 = blockIdx.y * 32;
    const int tx = threadIdx.x;
    const int ty = threadIdx.y;

#pragma unroll
    for (int i = 0; i < 32; i += 8)
        t[ty + i][tx] = U[(size_t)(a0 + ty + i) * 65536 + c * 256 + d0 + tx];
    __syncthreads();
#pragma unroll
    for (int i = 0; i < 32; i += 8) {
        int dl = ty + i;
        size_t rowbase = ((size_t)(d0 + dl) * 256 + c) * 256;
        Upt[rowbase + a0 + tx] = __float2half(t[tx][dl]);
    }
}

__global__ void build_h(const float* __restrict__ x, const float* __restrict__ sent,
                        float* __restrict__ h)
{
    int idx = blockIdx.x * blockDim.x + threadIdx.x;
    int rowi = idx >> 9;
    int e = idx & 511;
    int t = rowi & 127;
    int b = rowi >> 7;
    h[idx] = (t == 0) ? sent[e] : x[((size_t)(b * 127 + t - 1)) * 512 + e];
}

__global__ void write_mask(const int* __restrict__ mask, float* __restrict__ outm)
{
    int i = blockIdx.x * blockDim.x + threadIdx.x;
    if (i < 1024) {
        int b = i >> 7, t = i & 127;
        outm[i] = (t == 0) ? 1.0f : (float)mask[b * 127 + t - 1];
    }
}

// ===========================================================================
extern "C" void kernel_launch(void* const* d_in, const int* in_sizes, int n_in,
                              void* d_out, int out_size)
{
    (void)in_sizes; (void)n_in; (void)out_size;

    const float* x    = (const float*)d_in[0];
    const int*   mask = (const int*)d_in[2];
    const float* sent = (const float*)d_in[20];
    float* out = (float*)d_out;

    float* h;
    f16 *projb, *Up, *t1, *t2;
    cudaGetSymbolAddress((void**)&h,     g_h);
    cudaGetSymbolAddress((void**)&projb, g_projb);
    cudaGetSymbolAddress((void**)&Up,    g_Up);
    cudaGetSymbolAddress((void**)&t1,    g_t1);
    cudaGetSymbolAddress((void**)&t2,    g_t2);

    const int SMEM = 65536 + 2 * 16384 + 1024;   // 99328 -> 2 CTAs/SM
    cudaFuncSetAttribute(stage1_k, cudaFuncAttributeMaxDynamicSharedMemorySize, SMEM);
    cudaFuncSetAttribute(stage23_k<2, 0>, cudaFuncAttributeMaxDynamicSharedMemorySize, SMEM);
    cudaFuncSetAttribute(stage23_k<1, 1>, cudaFuncAttributeMaxDynamicSharedMemorySize, SMEM);

    ProjArgs pa;
    for (int i = 0; i < 7; i++) {
        pa.W[i]    = (const float*)d_in[3 + 2 * i];
        pa.bias[i] = (const float*)d_in[4 + 2 * i];
    }

    PtrU us;
    us.p[0] = (const float*)d_in[17];
    us.p[1] = (const float*)d_in[18];
    us.p[2] = (const float*)d_in[19];

    // branches: 0 sib_head, 1 sib_dep, 2 cop_head, 3 cop_dep,
    //           4 gp_head, 5 gp_dep, 6 gp_head_dep
    Ptr3 vp = {{ projb + 1 * PB, projb + 3 * PB, projb + 6 * PB }};
    Ptr3 wp = {{ projb + 1 * PB, projb + 2 * PB, projb + 5 * PB }};
    Ptr3 t1p = {{ t1, t1 + T1S, t1 + 2 * T1S }};
    Ptr3 t2p = {{ t2, t2 + T2S, t2 + 2 * T2S }};

    // launch order: profiled slot (index 3) = stage1 (all tris)
    build_h<<<2048, 256>>>(x, sent, h);                              // 0
    proj_gemm<<<dim3(2, 8, 7), 256>>>(pa, h, projb);                 // 1
    uconv<<<dim3(8, 8, 768), dim3(32, 8)>>>(us, Up);                 // 2
    stage1_k<<<dim3(8, 64, 3), 256, SMEM>>>(projb, Up, t1);          // 3 <- ncu

    // stage2: A = v[b] (resident), B = t1[bi], out t2[tri][bi] f16
    stage23_k<2, 0><<<dim3(1024, 3), 256, SMEM>>>(
        vp, 32768ULL, 7,
        t1p, 65536ULL, 0,
        t2, T2S, 32768ULL, 256);

    // stage3: A = t2[tri][bi] (resident), B = w[b], out f32 scores
    stage23_k<1, 1><<<dim3(1024, 3), 256, SMEM>>>(
        t2p, 32768ULL, 0,
        wp, 32768ULL, 7,
        out, 16777216ULL, 16384ULL, 128);

    write_mask<<<4, 256>>>(mask, out + (size_t)3 * 16777216);
}

// round 12
// speedup vs baseline: 1.8518x; 1.0198x over previous
#include <cuda_runtime.h>
#include <cuda_fp16.h>
#include <cstdint>
#include <math.h>

typedef __half f16;

// ===========================================================================
// TriParser, fp16 HMMA (f32 accum).
//   build_h16: h = [sentinel; x] -> hi|lo f16 [1024, 1024]
//   prep: U[a,c,d] -> Up rows r=d*256+c, cols a f16 [65536,256]
//         W[512,256] -> Wp[256, hi512|lo512] f16 (transposed, split)
//   proj (split 3-product HMMA, fp32-accurate): elu(h@W+b) -> f16 [1024,256]
//   stage1: t1[bi][d][c] = u @ Up^T        (A resident, 2 CTA/SM)
//   stage2: t2[bi][j][d] = v[b] @ t1[bi]^T (v resident, 2 tokens/CTA)
//   stage3: s[bi][j][k]  = t2[bi] @ w[b]^T (w resident, 2 tokens/CTA, f32 out)
// ===========================================================================

__device__ f16 g_h16[1024 * 1024];                     // 2 MB (hi|lo)
__device__ f16 g_Wp[7 * 256 * 1024];                   // 3.5 MB (hi|lo)
__device__ f16 g_projb[7 * 1024 * 256];                // 3.5 MB
__device__ f16 g_Up[3ull * 65536 * 256];               // 96 MB
__device__ f16 g_t1[3ull * 1024 * 65536];              // 402 MB
__device__ f16 g_t2[3ull * 1024 * 128 * 256];          // 201 MB

static const size_t PB  = 1024 * 256;
static const size_t PBW = 256 * 1024;
static const size_t UPS = (size_t)65536 * 256;
static const size_t T1S = (size_t)1024 * 65536;
static const size_t T2S = (size_t)1024 * 32768;

__device__ __forceinline__ uint32_t smem_u32(const void* p) {
    uint32_t a;
    asm("{ .reg .u64 t; cvta.to.shared.u64 t, %1; cvt.u32.u64 %0, t; }"
        : "=r"(a) : "l"(p));
    return a;
}

#define SW128(o) ((o) ^ (((o) >> 3) & 0x70))

__device__ __forceinline__ void ldm_x4(uint32_t* r, uint32_t addr) {
    asm volatile("ldmatrix.sync.aligned.m8n8.x4.shared.b16 {%0,%1,%2,%3}, [%4];"
                 : "=r"(r[0]), "=r"(r[1]), "=r"(r[2]), "=r"(r[3]) : "r"(addr));
}

__device__ __forceinline__ void mma16816(float* c, const uint32_t* a, const uint32_t* b) {
    asm volatile(
        "mma.sync.aligned.m16n8k16.row.col.f32.f16.f16.f32 "
        "{%0,%1,%2,%3}, {%4,%5,%6,%7}, {%8,%9}, {%0,%1,%2,%3};"
        : "+f"(c[0]), "+f"(c[1]), "+f"(c[2]), "+f"(c[3])
        : "r"(a[0]), "r"(a[1]), "r"(a[2]), "r"(a[3]), "r"(b[0]), "r"(b[1]));
}

__device__ __forceinline__ void cpa16(uint32_t dst, const void* src) {
    asm volatile("cp.async.cg.shared.global [%0], [%1], 16;" :: "r"(dst), "l"(src) : "memory");
}
#define CP_COMMIT() asm volatile("cp.async.commit_group;" ::: "memory")
#define CP_WAIT1()  asm volatile("cp.async.wait_group 1;" ::: "memory")
#define CP_WAIT0()  asm volatile("cp.async.wait_group 0;" ::: "memory")

// PLAIN K64 tile, 128 rows (16KB): rows x 128B, SW128. src rowstride rs f16.
__device__ __forceinline__ void load_plain(const f16* __restrict__ g, int rs, int c64,
                                           uint32_t dst, int tid) {
#pragma unroll
    for (int i = 0; i < 4; i++) {
        int idx = tid + i * 256;
        int row = idx >> 3, seg = idx & 7;
        cpa16(dst + SW128(row * 128 + seg * 16), g + (size_t)row * rs + c64 * 64 + seg * 8);
    }
}

// SPLIT K32 tile (16KB): 128 rows x (hi 64B | lo 64B). hi col c32*32, lo at +loOff.
__device__ __forceinline__ void load_split(const f16* __restrict__ g, int rs, int loOff,
                                           int c32, uint32_t dst, int tid) {
#pragma unroll
    for (int i = 0; i < 4; i++) {
        int idx = tid + i * 256;
        int row = idx >> 3, seg = idx & 7;
        int col = (seg < 4) ? c32 * 32 + seg * 8 : loOff + c32 * 32 + (seg - 4) * 8;
        cpa16(dst + SW128(row * 128 + seg * 16), g + (size_t)row * rs + col);
    }
}

// One K64 unit: D[32 x 128] per warp, plain operands (A at ab, B at bb).
__device__ __forceinline__ void mma_unit(uint32_t ab, uint32_t bb,
                                         float (&acc)[2][8][4],
                                         int aLB, int bLB, int wm, int wn) {
#pragma unroll
    for (int kk = 0; kk < 4; kk++) {
        uint32_t aq[2][4], bq[4][4];
#pragma unroll
        for (int mi = 0; mi < 2; mi++) {
            int off = aLB + (wm * 32 + mi * 16) * 128 + kk * 32;
            ldm_x4(aq[mi], ab + SW128(off));
        }
#pragma unroll
        for (int nj = 0; nj < 4; nj++) {
            int off = bLB + (wn * 64 + nj * 16) * 128 + kk * 32;
            ldm_x4(bq[nj], bb + SW128(off));
        }
#pragma unroll
        for (int mi = 0; mi < 2; mi++)
#pragma unroll
            for (int nj = 0; nj < 4; nj++) {
                mma16816(acc[mi][nj * 2],     aq[mi], &bq[nj][0]);
                mma16816(acc[mi][nj * 2 + 1], aq[mi], &bq[nj][2]);
            }
    }
}

#define ZERO_ACC(acc) \
    { _Pragma("unroll") for (int i = 0; i < 2; i++) \
      _Pragma("unroll") for (int j = 0; j < 8; j++) \
      _Pragma("unroll") for (int k = 0; k < 4; k++) acc[i][j][k] = 0.0f; }

#define WARP_IDS \
    const int tid = threadIdx.x; \
    const int lane = tid & 31; \
    const int warp = tid >> 5; \
    const int wm = warp >> 1, wn = warp & 1; \
    const int aLB = ((lane & 15) * 128) + ((lane >> 4) * 16); \
    const int bLB = (((lane & 7) + ((lane >> 4) << 3)) * 128) + (((lane >> 3) & 1) * 16); \
    const int gRow = lane >> 2; \
    const int cPair = (lane & 3) * 2;

// ===========================================================================
// Stage1 (all tris): t1 = u @ Up^T. grid (8 M, 64 Ngrp, 3 tri), 2 CTA/SM.
// ===========================================================================
__global__ __launch_bounds__(256, 2)
void stage1_k(const f16* __restrict__ projb, const f16* __restrict__ Up,
              f16* __restrict__ T1)
{
    extern __shared__ char dsm[];
    const uint32_t sraw = smem_u32(dsm);
    const uint32_t sb = (sraw + 1023u) & ~1023u;
    const uint32_t sbA = sb;
    const uint32_t sbB = sb + 65536;

    WARP_IDS

    const int tri = blockIdx.z;
    const f16* Au = projb + (size_t)(2 * tri) * PB + (size_t)blockIdx.x * 128 * 256;
    const f16* Ub = Up + (size_t)tri * UPS;
    f16* T1t = T1 + (size_t)tri * T1S;

    auto issueU = [&](int u) {
        if (u < 32) {
            int nt = u >> 2, ch = u & 3;
            load_plain(Ub + ((size_t)blockIdx.y * 8 + nt) * 128 * 256, 256, ch,
                       sbB + (u & 1) * 16384, tid);
        }
        CP_COMMIT();
    };

#pragma unroll
    for (int ch = 0; ch < 4; ch++)
        load_plain(Au, 256, ch, sbA + ch * 16384, tid);
    issueU(0);
    issueU(1);

    float acc[2][8][4];
    ZERO_ACC(acc);

    for (int u = 0; u < 32; u++) {
        if (u < 31) CP_WAIT1(); else CP_WAIT0();
        __syncthreads();
        mma_unit(sbA + (u & 3) * 16384, sbB + (u & 1) * 16384, acc, aLB, bLB, wm, wn);
        if (u < 30) { __syncthreads(); issueU(u + 2); }

        if ((u & 3) == 3) {
            int nt = u >> 2;
            size_t colBase = ((size_t)blockIdx.y * 8 + nt) * 128;
#pragma unroll
            for (int mi = 0; mi < 2; mi++) {
                int rbase = blockIdx.x * 128 + wm * 32 + mi * 16 + gRow;
#pragma unroll
                for (int f = 0; f < 8; f++) {
                    int nloc = wn * 64 + f * 8 + cPair;
#pragma unroll
                    for (int hh = 0; hh < 2; hh++) {
                        size_t row = (size_t)(rbase + hh * 8);
                        __half2 p;
                        p.x = __float2half(acc[mi][f][hh * 2 + 0]);
                        p.y = __float2half(acc[mi][f][hh * 2 + 1]);
                        *(__half2*)(T1t + row * 65536 + colBase + nloc) = p;
                        acc[mi][f][hh * 2 + 0] = 0.0f;
                        acc[mi][f][hh * 2 + 1] = 0.0f;
                    }
                }
            }
        }
    }
}

// ===========================================================================
// Stage2 (all tris): t2[tok][j][d] = v[b] @ t1[tok]^T. 2 tokens/CTA.
// grid (512, 3). v resident (64KB); t1 streamed 16 tiles.
// ===========================================================================
struct Ptr3 { const f16* p[3]; };

__global__ __launch_bounds__(256, 2)
void stage2_k(Ptr3 vp, const f16* __restrict__ T1, f16* __restrict__ T2)
{
    extern __shared__ char dsm[];
    const uint32_t sraw = smem_u32(dsm);
    const uint32_t sb = (sraw + 1023u) & ~1023u;
    const uint32_t sbA = sb;
    const uint32_t sbB = sb + 65536;

    WARP_IDS

    const int z = blockIdx.x;
    const int tri = blockIdx.y;
    const f16* Av = vp.p[tri] + (size_t)(z >> 6) * 32768;
    const f16* T1t = T1 + (size_t)tri * T1S;
    f16* T2t = T2 + (size_t)tri * T2S;

    auto issueU = [&](int g) {
        if (g < 16) {
            int tt = g >> 3, nh = (g >> 2) & 1, ch = g & 3;
            const f16* src = T1t + (size_t)(2 * z + tt) * 65536 + (size_t)nh * 128 * 256;
            load_plain(src, 256, ch, sbB + (g & 1) * 16384, tid);
        }
        CP_COMMIT();
    };

#pragma unroll
    for (int ch = 0; ch < 4; ch++)
        load_plain(Av, 256, ch, sbA + ch * 16384, tid);
    issueU(0);
    issueU(1);

    float acc[2][8][4];
    ZERO_ACC(acc);

#pragma unroll
    for (int g = 0; g < 16; g++) {
        if (g < 15) CP_WAIT1(); else CP_WAIT0();
        __syncthreads();
        mma_unit(sbA + (g & 3) * 16384, sbB + (g & 1) * 16384, acc, aLB, bLB, wm, wn);
        if (g < 14) { __syncthreads(); issueU(g + 2); }

        if ((g & 3) == 3) {
            int tt = g >> 3, nh = (g >> 2) & 1;
            f16* Cb = T2t + (size_t)(2 * z + tt) * 32768;
#pragma unroll
            for (int mi = 0; mi < 2; mi++) {
                int rbase = wm * 32 + mi * 16 + gRow;
#pragma unroll
                for (int f = 0; f < 8; f++) {
                    int col = nh * 128 + wn * 64 + f * 8 + cPair;
#pragma unroll
                    for (int hh = 0; hh < 2; hh++) {
                        size_t row = (size_t)(rbase + hh * 8);
                        __half2 p;
                        p.x = __float2half(acc[mi][f][hh * 2 + 0]);
                        p.y = __float2half(acc[mi][f][hh * 2 + 1]);
                        *(__half2*)(Cb + row * 256 + col) = p;
                        acc[mi][f][hh * 2 + 0] = 0.0f;
                        acc[mi][f][hh * 2 + 1] = 0.0f;
                    }
                }
            }
        }
    }
}

// ===========================================================================
// Stage3 (all tris): s[tok][j][k] = t2[tok] @ w[b]^T. 2 tokens/CTA.
// grid (512, 3). w resident as B (64KB); t2 streamed as A (8 tiles). f32 out.
// ===========================================================================
__global__ __launch_bounds__(256, 2)
void stage3_k(Ptr3 wp, const f16* __restrict__ T2, float* __restrict__ OUT)
{
    extern __shared__ char dsm[];
    const uint32_t sraw = smem_u32(dsm);
    const uint32_t sb = (sraw + 1023u) & ~1023u;
    const uint32_t sbB = sb;          // resident w
    const uint32_t sbA = sb + 65536;  // streamed t2

    WARP_IDS

    const int z = blockIdx.x;
    const int tri = blockIdx.y;
    const f16* Bw = wp.p[tri] + (size_t)(z >> 6) * 32768;
    const f16* T2t = T2 + (size_t)tri * T2S;
    float* Ot = OUT + (size_t)tri * 16777216;

    auto issueA = [&](int g) {
        if (g < 8) {
            int tt = g >> 2, ch = g & 3;
            load_plain(T2t + (size_t)(2 * z + tt) * 32768, 256, ch,
                       sbA + (g & 1) * 16384, tid);
        }
        CP_COMMIT();
    };

#pragma unroll
    for (int ch = 0; ch < 4; ch++)
        load_plain(Bw, 256, ch, sbB + ch * 16384, tid);
    issueA(0);
    issueA(1);

    float acc[2][8][4];
    ZERO_ACC(acc);

#pragma unroll
    for (int g = 0; g < 8; g++) {
        if (g < 7) CP_WAIT1(); else CP_WAIT0();
        __syncthreads();
        mma_unit(sbA + (g & 1) * 16384, sbB + (g & 3) * 16384, acc, aLB, bLB, wm, wn);
        if (g < 6) { __syncthreads(); issueA(g + 2); }

        if ((g & 3) == 3) {
            int tt = g >> 2;
            float* Cb = Ot + (size_t)(2 * z + tt) * 16384;
#pragma unroll
            for (int mi = 0; mi < 2; mi++) {
                int rbase = wm * 32 + mi * 16 + gRow;
#pragma unroll
                for (int f = 0; f < 8; f++) {
                    int col = wn * 64 + f * 8 + cPair;
#pragma unroll
                    for (int hh = 0; hh < 2; hh++) {
                        size_t row = (size_t)(rbase + hh * 8);
                        *(float2*)(Cb + row * 128 + col) =
                            make_float2(acc[mi][f][hh * 2 + 0], acc[mi][f][hh * 2 + 1]);
                        acc[mi][f][hh * 2 + 0] = 0.0f;
                        acc[mi][f][hh * 2 + 1] = 0.0f;
                    }
                }
            }
        }
    }
}

// ===========================================================================
// Projection, split 3-product HMMA (fp32-accurate): elu(h@W+b) -> f16 [1024,256]
// grid (8 M, 2 N, 7 branch). K=512 = 16 K32 steps, 2-deep.
// ===========================================================================
struct BiasArgs { const float* b[7]; };

__global__ __launch_bounds__(256, 2)
void proj_mma(BiasArgs ba, const f16* __restrict__ h16, const f16* __restrict__ Wp,
              f16* __restrict__ projb)
{
    extern __shared__ char dsm[];
    const uint32_t sraw = smem_u32(dsm);
    const uint32_t sb = (sraw + 1023u) & ~1023u;

    WARP_IDS

    const int br = blockIdx.z;
    const f16* A = h16 + (size_t)blockIdx.x * 128 * 1024;
    const f16* B = Wp + (size_t)br * PBW + (size_t)blockIdx.y * 128 * 1024;

    auto issue = [&](int s) {
        if (s < 16) {
            uint32_t buf = sb + (s & 1) * 32768;
            load_split(A, 1024, 512, s, buf, tid);
            load_split(B, 1024, 512, s, buf + 16384, tid);
        }
        CP_COMMIT();
    };
    issue(0); issue(1);

    float acc[2][8][4];
    ZERO_ACC(acc);

#pragma unroll
    for (int s = 0; s < 16; s++) {
        if (s < 15) CP_WAIT1(); else CP_WAIT0();
        __syncthreads();
        uint32_t ab = sb + (s & 1) * 32768;
        uint32_t bb = ab + 16384;
#pragma unroll
        for (int kk = 0; kk < 2; kk++) {
            uint32_t ah[2][4], al[2][4], bh[4][4], bl[4][4];
#pragma unroll
            for (int mi = 0; mi < 2; mi++) {
                int off = aLB + (wm * 32 + mi * 16) * 128 + kk * 32;
                ldm_x4(ah[mi], ab + SW128(off));
                ldm_x4(al[mi], ab + SW128(off + 64));
            }
#pragma unroll
            for (int nj = 0; nj < 4; nj++) {
                int off = bLB + (wn * 64 + nj * 16) * 128 + kk * 32;
                ldm_x4(bh[nj], bb + SW128(off));
                ldm_x4(bl[nj], bb + SW128(off + 64));
            }
#pragma unroll
            for (int mi = 0; mi < 2; mi++)
#pragma unroll
                for (int nj = 0; nj < 4; nj++) {
                    mma16816(acc[mi][nj * 2],     ah[mi], &bh[nj][0]);
                    mma16816(acc[mi][nj * 2 + 1], ah[mi], &bh[nj][2]);
                    mma16816(acc[mi][nj * 2],     ah[mi], &bl[nj][0]);
                    mma16816(acc[mi][nj * 2 + 1], ah[mi], &bl[nj][2]);
                    mma16816(acc[mi][nj * 2],     al[mi], &bh[nj][0]);
                    mma16816(acc[mi][nj * 2 + 1], al[mi], &bh[nj][2]);
                }
        }
        if (s < 14) { __syncthreads(); issue(s + 2); }
    }

    const float* bias = ba.b[br];
    f16* Co = projb + (size_t)br * PB;
#pragma unroll
    for (int mi = 0; mi < 2; mi++) {
        int rbase = blockIdx.x * 128 + wm * 32 + mi * 16 + gRow;
#pragma unroll
        for (int f = 0; f < 8; f++) {
            int col = blockIdx.y * 128 + wn * 64 + f * 8 + cPair;
#pragma unroll
            for (int hh = 0; hh < 2; hh++) {
                int row = rbase + hh * 8;
                float v0 = acc[mi][f][hh * 2 + 0] + bias[col];
                float v1 = acc[mi][f][hh * 2 + 1] + bias[col + 1];
                v0 = v0 > 0.f ? v0 : expm1f(v0);
                v1 = v1 > 0.f ? v1 : expm1f(v1);
                __half2 p;
                p.x = __float2half(v0);
                p.y = __float2half(v1);
                *(__half2*)(Co + (size_t)row * 256 + col) = p;
            }
        }
    }
}

// ===========================================================================
// Prep kernel: z < 768 -> Up permute; z >= 768 -> W transpose+split.
// ===========================================================================
struct PtrU { const float* p[3]; };
struct PtrW { const float* p[7]; };

__global__ void prep_k(PtrU Us, f16* __restrict__ Up, PtrW Ws, f16* __restrict__ Wp)
{
    __shared__ float t[32][33];
    const int zz = blockIdx.z;
    const int tx = threadIdx.x;
    const int ty = threadIdx.y;

    if (zz < 768) {
        const int tri = zz >> 8;
        const int c = zz & 255;
        const float* U = Us.p[tri];
        f16* Upt = Up + (size_t)tri * UPS;
        const int d0 = blockIdx.x * 32;
        const int a0 = blockIdx.y * 32;
#pragma unroll
        for (int i = 0; i < 32; i += 8)
            t[ty + i][tx] = U[(size_t)(a0 + ty + i) * 65536 + c * 256 + d0 + tx];
        __syncthreads();
#pragma unroll
        for (int i = 0; i < 32; i += 8) {
            int dl = ty + i;
            size_t rowbase = ((size_t)(d0 + dl) * 256 + c) * 256;
            Upt[rowbase + a0 + tx] = __float2half(t[tx][dl]);
        }
    } else {
        const int br = zz - 768;
        const float* W = Ws.p[br];
        f16* Wpt = Wp + (size_t)br * PBW;
        for (int t2i = 0; t2i < 2; t2i++) {
            int tile = ((blockIdx.y * 8 + blockIdx.x) * 2 + t2i);
            int k0 = (tile >> 3) * 32;
            int n0 = (tile & 7) * 32;
            __syncthreads();
#pragma unroll
            for (int i = 0; i < 32; i += 8)
                t[ty + i][tx] = W[(size_t)(k0 + ty + i) * 256 + n0 + tx];
            __syncthreads();
#pragma unroll
            for (int i = 0; i < 32; i += 8) {
                int dl = ty + i;
                float v = t[tx][dl];
                f16 hb = __float2half(v);
                f16 lb = __float2half(v - __half2float(hb));
                size_t rowbase = (size_t)(n0 + dl) * 1024;
                Wpt[rowbase + k0 + tx] = hb;
                Wpt[rowbase + 512 + k0 + tx] = lb;
            }
        }
    }
}

__global__ void build_h16(const float* __restrict__ x, const float* __restrict__ sent,
                          f16* __restrict__ h16)
{
    int idx = blockIdx.x * blockDim.x + threadIdx.x;   // 1024*512
    int rowi = idx >> 9;
    int e = idx & 511;
    int t = rowi & 127;
    int b = rowi >> 7;
    float v = (t == 0) ? sent[e] : x[((size_t)(b * 127 + t - 1)) * 512 + e];
    f16 hb = __float2half(v);
    f16 lb = __float2half(v - __half2float(hb));
    h16[(size_t)rowi * 1024 + e] = hb;
    h16[(size_t)rowi * 1024 + 512 + e] = lb;
}

__global__ void write_mask(const int* __restrict__ mask, float* __restrict__ outm)
{
    int i = blockIdx.x * blockDim.x + threadIdx.x;
    if (i < 1024) {
        int b = i >> 7, t = i & 127;
        outm[i] = (t == 0) ? 1.0f : (float)mask[b * 127 + t - 1];
    }
}

// ===========================================================================
extern "C" void kernel_launch(void* const* d_in, const int* in_sizes, int n_in,
                              void* d_out, int out_size)
{
    (void)in_sizes; (void)n_in; (void)out_size;

    const float* x    = (const float*)d_in[0];
    const int*   mask = (const int*)d_in[2];
    const float* sent = (const float*)d_in[20];
    float* out = (float*)d_out;

    f16 *h16, *Wpb, *projb, *Up, *t1, *t2;
    cudaGetSymbolAddress((void**)&h16,   g_h16);
    cudaGetSymbolAddress((void**)&Wpb,   g_Wp);
    cudaGetSymbolAddress((void**)&projb, g_projb);
    cudaGetSymbolAddress((void**)&Up,    g_Up);
    cudaGetSymbolAddress((void**)&t1,    g_t1);
    cudaGetSymbolAddress((void**)&t2,    g_t2);

    const int SMEM  = 65536 + 2 * 16384 + 1024;   // 99328 -> 2 CTAs/SM
    const int SMEMP = 2 * 32768 + 1024;           // 66560 -> 2 CTAs/SM
    cudaFuncSetAttribute(stage1_k, cudaFuncAttributeMaxDynamicSharedMemorySize, SMEM);
    cudaFuncSetAttribute(stage2_k, cudaFuncAttributeMaxDynamicSharedMemorySize, SMEM);
    cudaFuncSetAttribute(stage3_k, cudaFuncAttributeMaxDynamicSharedMemorySize, SMEM);
    cudaFuncSetAttribute(proj_mma, cudaFuncAttributeMaxDynamicSharedMemorySize, SMEMP);

    BiasArgs ba;
    PtrW ws;
    for (int i = 0; i < 7; i++) {
        ws.p[i] = (const float*)d_in[3 + 2 * i];
        ba.b[i] = (const float*)d_in[4 + 2 * i];
    }
    PtrU us;
    us.p[0] = (const float*)d_in[17];
    us.p[1] = (const float*)d_in[18];
    us.p[2] = (const float*)d_in[19];

    // branches: 0 sib_head, 1 sib_dep, 2 cop_head, 3 cop_dep,
    //           4 gp_head, 5 gp_dep, 6 gp_head_dep
    Ptr3 vp = {{ projb + 1 * PB, projb + 3 * PB, projb + 6 * PB }};
    Ptr3 wp = {{ projb + 1 * PB, projb + 2 * PB, projb + 5 * PB }};

    build_h16<<<2048, 256>>>(x, sent, h16);                          // 0
    prep_k<<<dim3(8, 8, 775), dim3(32, 8)>>>(us, Up, ws, Wpb);       // 1
    proj_mma<<<dim3(8, 2, 7), 256, SMEMP>>>(ba, h16, Wpb, projb);    // 2
    stage1_k<<<dim3(8, 64, 3), 256, SMEM>>>(projb, Up, t1);          // 3 <- ncu
    stage2_k<<<dim3(512, 3), 256, SMEM>>>(vp, t1, t2);               // 4
    stage3_k<<<dim3(512, 3), 256, SMEM>>>(wp, t2, out);              // 5
    write_mask<<<4, 256>>>(mask, out + (size_t)3 * 16777216);        // 6
}

// round 13
// speedup vs baseline: 1.9420x; 1.0487x over previous
#include <cuda_runtime.h>
#include <cuda_fp16.h>
#include <cstdint>
#include <math.h>

typedef __half f16;

// ===========================================================================
// TriParser, fp16 HMMA (f32 accum).
//   build_h16: h = [sentinel; x] -> hi|lo f16 [1024, 1024]
//   prep: U -> Up rows r=d*256+c, cols a f16 [65536,256]; W -> Wp split [256,1024]
//   proj (split 3-product HMMA): elu(h@W+b) -> f16 [1024,256]
//   stage1: t1[bi][d][c] = u @ Up^T
//   stage2: t2[bi][j][d] = v[b] @ t1[bi]^T
//   stage3: s[bi][j][k]  = t2[bi] @ w[b]^T  (f32 out)
// Stage kernels: 128 thr, 4 warps, 64x64 warp tiles (LDSM:MMA = 0.25), 2 CTA/SM.
// ===========================================================================

__device__ f16 g_h16[1024 * 1024];                     // 2 MB (hi|lo)
__device__ f16 g_Wp[7 * 256 * 1024];                   // 3.5 MB (hi|lo)
__device__ f16 g_projb[7 * 1024 * 256];                // 3.5 MB
__device__ f16 g_Up[3ull * 65536 * 256];               // 96 MB
__device__ f16 g_t1[3ull * 1024 * 65536];              // 402 MB
__device__ f16 g_t2[3ull * 1024 * 128 * 256];          // 201 MB

static const size_t PB  = 1024 * 256;
static const size_t PBW = 256 * 1024;
static const size_t UPS = (size_t)65536 * 256;
static const size_t T1S = (size_t)1024 * 65536;
static const size_t T2S = (size_t)1024 * 32768;

__device__ __forceinline__ uint32_t smem_u32(const void* p) {
    uint32_t a;
    asm("{ .reg .u64 t; cvta.to.shared.u64 t, %1; cvt.u32.u64 %0, t; }"
        : "=r"(a) : "l"(p));
    return a;
}

#define SW128(o) ((o) ^ (((o) >> 3) & 0x70))

__device__ __forceinline__ void ldm_x4(uint32_t* r, uint32_t addr) {
    asm volatile("ldmatrix.sync.aligned.m8n8.x4.shared.b16 {%0,%1,%2,%3}, [%4];"
                 : "=r"(r[0]), "=r"(r[1]), "=r"(r[2]), "=r"(r[3]) : "r"(addr));
}

__device__ __forceinline__ void mma16816(float* c, const uint32_t* a, const uint32_t* b) {
    asm volatile(
        "mma.sync.aligned.m16n8k16.row.col.f32.f16.f16.f32 "
        "{%0,%1,%2,%3}, {%4,%5,%6,%7}, {%8,%9}, {%0,%1,%2,%3};"
        : "+f"(c[0]), "+f"(c[1]), "+f"(c[2]), "+f"(c[3])
        : "r"(a[0]), "r"(a[1]), "r"(a[2]), "r"(a[3]), "r"(b[0]), "r"(b[1]));
}

__device__ __forceinline__ void cpa16(uint32_t dst, const void* src) {
    asm volatile("cp.async.cg.shared.global [%0], [%1], 16;" :: "r"(dst), "l"(src) : "memory");
}
#define CP_COMMIT() asm volatile("cp.async.commit_group;" ::: "memory")
#define CP_WAIT1()  asm volatile("cp.async.wait_group 1;" ::: "memory")
#define CP_WAIT0()  asm volatile("cp.async.wait_group 0;" ::: "memory")

// PLAIN K64 tile, 128 rows (16KB), NT threads.
template <int NT>
__device__ __forceinline__ void load_plain(const f16* __restrict__ g, int rs, int c64,
                                           uint32_t dst, int tid) {
#pragma unroll
    for (int i = 0; i < 1024 / NT; i++) {
        int idx = tid + i * NT;
        int row = idx >> 3, seg = idx & 7;
        cpa16(dst + SW128(row * 128 + seg * 16), g + (size_t)row * rs + c64 * 64 + seg * 8);
    }
}

// SPLIT K32 tile (16KB): 128 rows x (hi 64B | lo 64B), NT threads.
template <int NT>
__device__ __forceinline__ void load_split(const f16* __restrict__ g, int rs, int loOff,
                                           int c32, uint32_t dst, int tid) {
#pragma unroll
    for (int i = 0; i < 1024 / NT; i++) {
        int idx = tid + i * NT;
        int row = idx >> 3, seg = idx & 7;
        int col = (seg < 4) ? c32 * 32 + seg * 8 : loOff + c32 * 32 + (seg - 4) * 8;
        cpa16(dst + SW128(row * 128 + seg * 16), g + (size_t)row * rs + col);
    }
}

// One K64 unit, 64x64 warp tile (MI=4): D[64 x 64] per warp.
__device__ __forceinline__ void mma_unit4(uint32_t ab, uint32_t bb,
                                          float (&acc)[4][8][4],
                                          int aLB, int bLB, int wm, int wn) {
#pragma unroll
    for (int kk = 0; kk < 4; kk++) {
        uint32_t aq[4][4], bq[4][4];
#pragma unroll
        for (int mi = 0; mi < 4; mi++) {
            int off = aLB + (wm * 64 + mi * 16) * 128 + kk * 32;
            ldm_x4(aq[mi], ab + SW128(off));
        }
#pragma unroll
        for (int nj = 0; nj < 4; nj++) {
            int off = bLB + (wn * 64 + nj * 16) * 128 + kk * 32;
            ldm_x4(bq[nj], bb + SW128(off));
        }
#pragma unroll
        for (int mi = 0; mi < 4; mi++)
#pragma unroll
            for (int nj = 0; nj < 4; nj++) {
                mma16816(acc[mi][nj * 2],     aq[mi], &bq[nj][0]);
                mma16816(acc[mi][nj * 2 + 1], aq[mi], &bq[nj][2]);
            }
    }
}

#define ZERO_ACC4(acc) \
    { _Pragma("unroll") for (int i = 0; i < 4; i++) \
      _Pragma("unroll") for (int j = 0; j < 8; j++) \
      _Pragma("unroll") for (int k = 0; k < 4; k++) acc[i][j][k] = 0.0f; }

#define WARP_IDS \
    const int tid = threadIdx.x; \
    const int lane = tid & 31; \
    const int warp = tid >> 5; \
    const int wm = warp >> 1, wn = warp & 1; \
    const int aLB = ((lane & 15) * 128) + ((lane >> 4) * 16); \
    const int bLB = (((lane & 7) + ((lane >> 4) << 3)) * 128) + (((lane >> 3) & 1) * 16); \
    const int gRow = lane >> 2; \
    const int cPair = (lane & 3) * 2;

// ===========================================================================
// Stage1 (all tris): t1 = u @ Up^T. grid (8 M, 64 Ngrp, 3 tri), 128 thr, 2 CTA/SM.
// A [128x256] resident (64KB); 8 N-tiles x 4 K64 units, B 2x16KB stream.
// ===========================================================================
__global__ __launch_bounds__(128, 2)
void stage1_k(const f16* __restrict__ projb, const f16* __restrict__ Up,
              f16* __restrict__ T1)
{
    extern __shared__ char dsm[];
    const uint32_t sraw = smem_u32(dsm);
    const uint32_t sb = (sraw + 1023u) & ~1023u;
    const uint32_t sbA = sb;
    const uint32_t sbB = sb + 65536;

    WARP_IDS

    const int tri = blockIdx.z;
    const f16* Au = projb + (size_t)(2 * tri) * PB + (size_t)blockIdx.x * 128 * 256;
    const f16* Ub = Up + (size_t)tri * UPS;
    f16* T1t = T1 + (size_t)tri * T1S;

    auto issueU = [&](int u) {
        if (u < 32) {
            int nt = u >> 2, ch = u & 3;
            load_plain<128>(Ub + ((size_t)blockIdx.y * 8 + nt) * 128 * 256, 256, ch,
                            sbB + (u & 1) * 16384, tid);
        }
        CP_COMMIT();
    };

#pragma unroll
    for (int ch = 0; ch < 4; ch++)
        load_plain<128>(Au, 256, ch, sbA + ch * 16384, tid);
    issueU(0);
    issueU(1);

    float acc[4][8][4];
    ZERO_ACC4(acc);

    for (int u = 0; u < 32; u++) {
        if (u < 31) CP_WAIT1(); else CP_WAIT0();
        __syncthreads();
        mma_unit4(sbA + (u & 3) * 16384, sbB + (u & 1) * 16384, acc, aLB, bLB, wm, wn);
        if (u < 30) { __syncthreads(); issueU(u + 2); }

        if ((u & 3) == 3) {
            int nt = u >> 2;
            size_t colBase = ((size_t)blockIdx.y * 8 + nt) * 128;
#pragma unroll
            for (int mi = 0; mi < 4; mi++) {
                int rbase = blockIdx.x * 128 + wm * 64 + mi * 16 + gRow;
#pragma unroll
                for (int f = 0; f < 8; f++) {
                    int nloc = wn * 64 + f * 8 + cPair;
#pragma unroll
                    for (int hh = 0; hh < 2; hh++) {
                        size_t row = (size_t)(rbase + hh * 8);
                        __half2 p;
                        p.x = __float2half(acc[mi][f][hh * 2 + 0]);
                        p.y = __float2half(acc[mi][f][hh * 2 + 1]);
                        *(__half2*)(T1t + row * 65536 + colBase + nloc) = p;
                        acc[mi][f][hh * 2 + 0] = 0.0f;
                        acc[mi][f][hh * 2 + 1] = 0.0f;
                    }
                }
            }
        }
    }
}

// ===========================================================================
// Stage2 (all tris): t2[tok][j][d] = v[b] @ t1[tok]^T. 2 tokens/CTA.
// grid (512, 3), 128 thr. v resident (64KB); t1 streamed 16 tiles.
// ===========================================================================
struct Ptr3 { const f16* p[3]; };

__global__ __launch_bounds__(128, 2)
void stage2_k(Ptr3 vp, const f16* __restrict__ T1, f16* __restrict__ T2)
{
    extern __shared__ char dsm[];
    const uint32_t sraw = smem_u32(dsm);
    const uint32_t sb = (sraw + 1023u) & ~1023u;
    const uint32_t sbA = sb;
    const uint32_t sbB = sb + 65536;

    WARP_IDS

    const int z = blockIdx.x;
    const int tri = blockIdx.y;
    const f16* Av = vp.p[tri] + (size_t)(z >> 6) * 32768;
    const f16* T1t = T1 + (size_t)tri * T1S;
    f16* T2t = T2 + (size_t)tri * T2S;

    auto issueU = [&](int g) {
        if (g < 16) {
            int tt = g >> 3, nh = (g >> 2) & 1, ch = g & 3;
            const f16* src = T1t + (size_t)(2 * z + tt) * 65536 + (size_t)nh * 128 * 256;
            load_plain<128>(src, 256, ch, sbB + (g & 1) * 16384, tid);
        }
        CP_COMMIT();
    };

#pragma unroll
    for (int ch = 0; ch < 4; ch++)
        load_plain<128>(Av, 256, ch, sbA + ch * 16384, tid);
    issueU(0);
    issueU(1);

    float acc[4][8][4];
    ZERO_ACC4(acc);

#pragma unroll
    for (int g = 0; g < 16; g++) {
        if (g < 15) CP_WAIT1(); else CP_WAIT0();
        __syncthreads();
        mma_unit4(sbA + (g & 3) * 16384, sbB + (g & 1) * 16384, acc, aLB, bLB, wm, wn);
        if (g < 14) { __syncthreads(); issueU(g + 2); }

        if ((g & 3) == 3) {
            int tt = g >> 3, nh = (g >> 2) & 1;
            f16* Cb = T2t + (size_t)(2 * z + tt) * 32768;
#pragma unroll
            for (int mi = 0; mi < 4; mi++) {
                int rbase = wm * 64 + mi * 16 + gRow;
#pragma unroll
                for (int f = 0; f < 8; f++) {
                    int col = nh * 128 + wn * 64 + f * 8 + cPair;
#pragma unroll
                    for (int hh = 0; hh < 2; hh++) {
                        size_t row = (size_t)(rbase + hh * 8);
                        __half2 p;
                        p.x = __float2half(acc[mi][f][hh * 2 + 0]);
                        p.y = __float2half(acc[mi][f][hh * 2 + 1]);
                        *(__half2*)(Cb + row * 256 + col) = p;
                        acc[mi][f][hh * 2 + 0] = 0.0f;
                        acc[mi][f][hh * 2 + 1] = 0.0f;
                    }
                }
            }
        }
    }
}

// ===========================================================================
// Stage3 (all tris): s[tok][j][k] = t2[tok] @ w[b]^T. 2 tokens/CTA.
// grid (512, 3), 128 thr. w resident as B (64KB); t2 streamed as A. f32 out.
// ===========================================================================
__global__ __launch_bounds__(128, 2)
void stage3_k(Ptr3 wp, const f16* __restrict__ T2, float* __restrict__ OUT)
{
    extern __shared__ char dsm[];
    const uint32_t sraw = smem_u32(dsm);
    const uint32_t sb = (sraw + 1023u) & ~1023u;
    const uint32_t sbB = sb;          // resident w
    const uint32_t sbA = sb + 65536;  // streamed t2

    WARP_IDS

    const int z = blockIdx.x;
    const int tri = blockIdx.y;
    const f16* Bw = wp.p[tri] + (size_t)(z >> 6) * 32768;
    const f16* T2t = T2 + (size_t)tri * T2S;
    float* Ot = OUT + (size_t)tri * 16777216;

    auto issueA = [&](int g) {
        if (g < 8) {
            int tt = g >> 2, ch = g & 3;
            load_plain<128>(T2t + (size_t)(2 * z + tt) * 32768, 256, ch,
                            sbA + (g & 1) * 16384, tid);
        }
        CP_COMMIT();
    };

#pragma unroll
    for (int ch = 0; ch < 4; ch++)
        load_plain<128>(Bw, 256, ch, sbB + ch * 16384, tid);
    issueA(0);
    issueA(1);

    float acc[4][8][4];
    ZERO_ACC4(acc);

#pragma unroll
    for (int g = 0; g < 8; g++) {
        if (g < 7) CP_WAIT1(); else CP_WAIT0();
        __syncthreads();
        mma_unit4(sbA + (g & 1) * 16384, sbB + (g & 3) * 16384, acc, aLB, bLB, wm, wn);
        if (g < 6) { __syncthreads(); issueA(g + 2); }

        if ((g & 3) == 3) {
            int tt = g >> 2;
            float* Cb = Ot + (size_t)(2 * z + tt) * 16384;
#pragma unroll
            for (int mi = 0; mi < 4; mi++) {
                int rbase = wm * 64 + mi * 16 + gRow;
#pragma unroll
                for (int f = 0; f < 8; f++) {
                    int col = wn * 64 + f * 8 + cPair;
#pragma unroll
                    for (int hh = 0; hh < 2; hh++) {
                        size_t row = (size_t)(rbase + hh * 8);
                        *(float2*)(Cb + row * 128 + col) =
                            make_float2(acc[mi][f][hh * 2 + 0], acc[mi][f][hh * 2 + 1]);
                        acc[mi][f][hh * 2 + 0] = 0.0f;
                        acc[mi][f][hh * 2 + 1] = 0.0f;
                    }
                }
            }
        }
    }
}

// ===========================================================================
// Projection, split 3-product HMMA: elu(h@W+b) -> f16 [1024,256]
// grid (8 M, 2 N, 7 branch), 256 thr. K=512 = 16 K32 steps, 2-deep.
// ===========================================================================
struct BiasArgs { const float* b[7]; };

__global__ __launch_bounds__(256, 2)
void proj_mma(BiasArgs ba, const f16* __restrict__ h16, const f16* __restrict__ Wp,
              f16* __restrict__ projb)
{
    extern __shared__ char dsm[];
    const uint32_t sraw = smem_u32(dsm);
    const uint32_t sb = (sraw + 1023u) & ~1023u;

    WARP_IDS

    const int br = blockIdx.z;
    const f16* A = h16 + (size_t)blockIdx.x * 128 * 1024;
    const f16* B = Wp + (size_t)br * PBW + (size_t)blockIdx.y * 128 * 1024;

    auto issue = [&](int s) {
        if (s < 16) {
            uint32_t buf = sb + (s & 1) * 32768;
            load_split<256>(A, 1024, 512, s, buf, tid);
            load_split<256>(B, 1024, 512, s, buf + 16384, tid);
        }
        CP_COMMIT();
    };
    issue(0); issue(1);

    float acc[2][8][4];
#pragma unroll
    for (int i = 0; i < 2; i++)
#pragma unroll
        for (int j = 0; j < 8; j++)
#pragma unroll
            for (int k = 0; k < 4; k++) acc[i][j][k] = 0.0f;

#pragma unroll
    for (int s = 0; s < 16; s++) {
        if (s < 15) CP_WAIT1(); else CP_WAIT0();
        __syncthreads();
        uint32_t ab = sb + (s & 1) * 32768;
        uint32_t bb = ab + 16384;
#pragma unroll
        for (int kk = 0; kk < 2; kk++) {
            uint32_t ah[2][4], al[2][4], bh[4][4], bl[4][4];
#pragma unroll
            for (int mi = 0; mi < 2; mi++) {
                int off = aLB + (wm * 32 + mi * 16) * 128 + kk * 32;
                ldm_x4(ah[mi], ab + SW128(off));
                ldm_x4(al[mi], ab + SW128(off + 64));
            }
#pragma unroll
            for (int nj = 0; nj < 4; nj++) {
                int off = bLB + (wn * 64 + nj * 16) * 128 + kk * 32;
                ldm_x4(bh[nj], bb + SW128(off));
                ldm_x4(bl[nj], bb + SW128(off + 64));
            }
#pragma unroll
            for (int mi = 0; mi < 2; mi++)
#pragma unroll
                for (int nj = 0; nj < 4; nj++) {
                    mma16816(acc[mi][nj * 2],     ah[mi], &bh[nj][0]);
                    mma16816(acc[mi][nj * 2 + 1], ah[mi], &bh[nj][2]);
                    mma16816(acc[mi][nj * 2],     ah[mi], &bl[nj][0]);
                    mma16816(acc[mi][nj * 2 + 1], ah[mi], &bl[nj][2]);
                    mma16816(acc[mi][nj * 2],     al[mi], &bh[nj][0]);
                    mma16816(acc[mi][nj * 2 + 1], al[mi], &bh[nj][2]);
                }
        }
        if (s < 14) { __syncthreads(); issue(s + 2); }
    }

    const float* bias = ba.b[br];
    f16* Co = projb + (size_t)br * PB;
#pragma unroll
    for (int mi = 0; mi < 2; mi++) {
        int rbase = blockIdx.x * 128 + wm * 32 + mi * 16 + gRow;
#pragma unroll
        for (int f = 0; f < 8; f++) {
            int col = blockIdx.y * 128 + wn * 64 + f * 8 + cPair;
#pragma unroll
            for (int hh = 0; hh < 2; hh++) {
                int row = rbase + hh * 8;
                float v0 = acc[mi][f][hh * 2 + 0] + bias[col];
                float v1 = acc[mi][f][hh * 2 + 1] + bias[col + 1];
                v0 = v0 > 0.f ? v0 : expm1f(v0);
                v1 = v1 > 0.f ? v1 : expm1f(v1);
                __half2 p;
                p.x = __float2half(v0);
                p.y = __float2half(v1);
                *(__half2*)(Co + (size_t)row * 256 + col) = p;
            }
        }
    }
}

// ===========================================================================
// Prep kernel: z < 768 -> Up permute; z >= 768 -> W transpose+split.
// ===========================================================================
struct PtrU { const float* p[3]; };
struct PtrW { const float* p[7]; };

__global__ void prep_k(PtrU Us, f16* __restrict__ Up, PtrW Ws, f16* __restrict__ Wp)
{
    __shared__ float t[32][33];
    const int zz = blockIdx.z;
    const int tx = threadIdx.x;
    const int ty = threadIdx.y;

    if (zz < 768) {
        const int tri = zz >> 8;
        const int c = zz & 255;
        const float* U = Us.p[tri];
        f16* Upt = Up + (size_t)tri * UPS;
        const int d0 = blockIdx.x * 32;
        const int a0 = blockIdx.y * 32;
#pragma unroll
        for (int i = 0; i < 32; i += 8)
            t[ty + i][tx] = U[(size_t)(a0 + ty + i) * 65536 + c * 256 + d0 + tx];
        __syncthreads();
#pragma unroll
        for (int i = 0; i < 32; i += 8) {
            int dl = ty + i;
            size_t rowbase = ((size_t)(d0 + dl) * 256 + c) * 256;
            Upt[rowbase + a0 + tx] = __float2half(t[tx][dl]);
        }
    } else {
        const int br = zz - 768;
        const float* W = Ws.p[br];
        f16* Wpt = Wp + (size_t)br * PBW;
        for (int t2i = 0; t2i < 2; t2i++) {
            int tile = ((blockIdx.y * 8 + blockIdx.x) * 2 + t2i);
            int k0 = (tile >> 3) * 32;
            int n0 = (tile & 7) * 32;
            __syncthreads();
#pragma unroll
            for (int i = 0; i < 32; i += 8)
                t[ty + i][tx] = W[(size_t)(k0 + ty + i) * 256 + n0 + tx];
            __syncthreads();
#pragma unroll
            for (int i = 0; i < 32; i += 8) {
                int dl = ty + i;
                float v = t[tx][dl];
                f16 hb = __float2half(v);
                f16 lb = __float2half(v - __half2float(hb));
                size_t rowbase = (size_t)(n0 + dl) * 1024;
                Wpt[rowbase + k0 + tx] = hb;
                Wpt[rowbase + 512 + k0 + tx] = lb;
            }
        }
    }
}

__global__ void build_h16(const float* __restrict__ x, const float* __restrict__ sent,
                          f16* __restrict__ h16)
{
    int idx = blockIdx.x * blockDim.x + threadIdx.x;   // 1024*512
    int rowi = idx >> 9;
    int e = idx & 511;
    int t = rowi & 127;
    int b = rowi >> 7;
    float v = (t == 0) ? sent[e] : x[((size_t)(b * 127 + t - 1)) * 512 + e];
    f16 hb = __float2half(v);
    f16 lb = __float2half(v - __half2float(hb));
    h16[(size_t)rowi * 1024 + e] = hb;
    h16[(size_t)rowi * 1024 + 512 + e] = lb;
}

__global__ void write_mask(const int* __restrict__ mask, float* __restrict__ outm)
{
    int i = blockIdx.x * blockDim.x + threadIdx.x;
    if (i < 1024) {
        int b = i >> 7, t = i & 127;
        outm[i] = (t == 0) ? 1.0f : (float)mask[b * 127 + t - 1];
    }
}

// ===========================================================================
extern "C" void kernel_launch(void* const* d_in, const int* in_sizes, int n_in,
                              void* d_out, int out_size)
{
    (void)in_sizes; (void)n_in; (void)out_size;

    const float* x    = (const float*)d_in[0];
    const int*   mask = (const int*)d_in[2];
    const float* sent = (const float*)d_in[20];
    float* out = (float*)d_out;

    f16 *h16, *Wpb, *projb, *Up, *t1, *t2;
    cudaGetSymbolAddress((void**)&h16,   g_h16);
    cudaGetSymbolAddress((void**)&Wpb,   g_Wp);
    cudaGetSymbolAddress((void**)&projb, g_projb);
    cudaGetSymbolAddress((void**)&Up,    g_Up);
    cudaGetSymbolAddress((void**)&t1,    g_t1);
    cudaGetSymbolAddress((void**)&t2,    g_t2);

    const int SMEM  = 65536 + 2 * 16384 + 1024;   // 99328 -> 2 CTAs/SM
    const int SMEMP = 2 * 32768 + 1024;           // 66560 -> 2 CTAs/SM
    cudaFuncSetAttribute(stage1_k, cudaFuncAttributeMaxDynamicSharedMemorySize, SMEM);
    cudaFuncSetAttribute(stage2_k, cudaFuncAttributeMaxDynamicSharedMemorySize, SMEM);
    cudaFuncSetAttribute(stage3_k, cudaFuncAttributeMaxDynamicSharedMemorySize, SMEM);
    cudaFuncSetAttribute(proj_mma, cudaFuncAttributeMaxDynamicSharedMemorySize, SMEMP);

    BiasArgs ba;
    PtrW ws;
    for (int i = 0; i < 7; i++) {
        ws.p[i] = (const float*)d_in[3 + 2 * i];
        ba.b[i] = (const float*)d_in[4 + 2 * i];
    }
    PtrU us;
    us.p[0] = (const float*)d_in[17];
    us.p[1] = (const float*)d_in[18];
    us.p[2] = (const float*)d_in[19];

    // branches: 0 sib_head, 1 sib_dep, 2 cop_head, 3 cop_dep,
    //           4 gp_head, 5 gp_dep, 6 gp_head_dep
    Ptr3 vp = {{ projb + 1 * PB, projb + 3 * PB, projb + 6 * PB }};
    Ptr3 wp = {{ projb + 1 * PB, projb + 2 * PB, projb + 5 * PB }};

    build_h16<<<2048, 256>>>(x, sent, h16);                          // 0
    prep_k<<<dim3(8, 8, 775), dim3(32, 8)>>>(us, Up, ws, Wpb);       // 1
    proj_mma<<<dim3(8, 2, 7), 256, SMEMP>>>(ba, h16, Wpb, projb);    // 2
    stage1_k<<<dim3(8, 64, 3), 128, SMEM>>>(projb, Up, t1);          // 3 <- ncu
    stage2_k<<<dim3(512, 3), 128, SMEM>>>(vp, t1, t2);               // 4
    stage3_k<<<dim3(512, 3), 128, SMEM>>>(wp, t2, out);              // 5
    write_mask<<<4, 256>>>(mask, out + (size_t)3 * 16777216);        // 6
}